// round 5
// baseline (speedup 1.0000x reference)
#include <cuda_runtime.h>
#include <cuda_bf16.h>
#include <math.h>
#include <stdint.h>

#define Bb 16
#define Ss 2048
#define Tt 1024
#define Ee 256
#define Dd 256
#define NSLICE 4
#define SLICE_S 512

// ---------------------------------------------------------------------------
// Scratch (allocation-free: device globals). bf16 hi/lo split representations.
// ---------------------------------------------------------------------------
__device__ __nv_bfloat16 g_encH[Bb * Ss * Ee];
__device__ __nv_bfloat16 g_encL[Bb * Ss * Ee];
__device__ __nv_bfloat16 g_decH[Bb * Tt * Dd];
__device__ __nv_bfloat16 g_decL[Bb * Tt * Dd];
__device__ __nv_bfloat16 g_projH[Bb * Ss * Dd];
__device__ __nv_bfloat16 g_projL[Bb * Ss * Dd];
__device__ __nv_bfloat16 g_ctxH[Bb * Tt * Ee];
__device__ __nv_bfloat16 g_ctxL[Bb * Tt * Ee];
__device__ __nv_bfloat16 g_WencTH[Dd * Ee];
__device__ __nv_bfloat16 g_WencTL[Dd * Ee];
__device__ __nv_bfloat16 g_WfinTH[Dd * (Ee + Dd)];
__device__ __nv_bfloat16 g_WfinTL[Dd * (Ee + Dd)];
__device__ int g_lengths[Bb];
__device__ float g_pctx[NSLICE * Bb * Tt * Ee];
__device__ float g_pm[NSLICE * Bb * Tt];
__device__ float g_pl[NSLICE * Bb * Tt];

// ---------------------------------------------------------------------------
// Helpers
// ---------------------------------------------------------------------------
__device__ __forceinline__ uint32_t smem_u32(const void* p) {
    uint32_t a;
    asm("{ .reg .u64 t; cvta.to.shared.u64 t, %1; cvt.u32.u64 %0, t; }"
        : "=r"(a) : "l"(p));
    return a;
}

__device__ __forceinline__ void mma16816(float* d, const uint32_t* a,
                                         const uint32_t* b) {
    asm volatile(
        "mma.sync.aligned.m16n8k16.row.col.f32.bf16.bf16.f32 "
        "{%0,%1,%2,%3}, {%4,%5,%6,%7}, {%8,%9}, {%0,%1,%2,%3};"
        : "+f"(d[0]), "+f"(d[1]), "+f"(d[2]), "+f"(d[3])
        : "r"(a[0]), "r"(a[1]), "r"(a[2]), "r"(a[3]), "r"(b[0]), "r"(b[1]));
}

__device__ __forceinline__ void ldsm_x4_nt(uint32_t& r0, uint32_t& r1,
                                           uint32_t& r2, uint32_t& r3,
                                           uint32_t addr) {
    asm volatile("ldmatrix.sync.aligned.m8n8.x4.shared.b16 "
                 "{%0,%1,%2,%3}, [%4];"
                 : "=r"(r0), "=r"(r1), "=r"(r2), "=r"(r3) : "r"(addr));
}

__device__ __forceinline__ void ldsm_x4_t(uint32_t& r0, uint32_t& r1,
                                          uint32_t& r2, uint32_t& r3,
                                          uint32_t addr) {
    asm volatile("ldmatrix.sync.aligned.m8n8.x4.trans.shared.b16 "
                 "{%0,%1,%2,%3}, [%4];"
                 : "=r"(r0), "=r"(r1), "=r"(r2), "=r"(r3) : "r"(addr));
}

// address for ldmatrix.x4 covering a 16row x 16col b16 tile at (row0, col0)
// quad 0: rows row0..+7 @col0 ; quad 1: rows +8..15 @col0
// quad 2: rows row0..+7 @col0+8 ; quad 3: rows +8..15 @col0+8
__device__ __forceinline__ uint32_t ldsm_addr(uint32_t base, int stride_b,
                                              int row0, int col0_b, int lane) {
    int quad = lane >> 3;
    int r = row0 + (lane & 7) + ((quad & 1) << 3);
    int c = col0_b + ((quad >> 1) << 4);
    return base + r * stride_b + c;
}

__device__ __forceinline__ void bsplit(float x, unsigned short& h,
                                       unsigned short& l) {
    __nv_bfloat16 hb = __float2bfloat16(x);
    __nv_bfloat16 lb = __float2bfloat16(x - __bfloat162float(hb));
    h = *(unsigned short*)&hb;
    l = *(unsigned short*)&lb;
}

__device__ __forceinline__ uint32_t pack2(unsigned short a, unsigned short b) {
    return (uint32_t)a | ((uint32_t)b << 16);
}

// ---------------------------------------------------------------------------
// Mask prologue (handles uint8 or int32 bool encodings)
// ---------------------------------------------------------------------------
__global__ void detect_lengths_kernel(const unsigned char* __restrict__ mask)
{
    __shared__ int s_flag;
    __shared__ int s_cnt[Bb];
    int tid = threadIdx.x;
    if (tid == 0) s_flag = 0;
    if (tid < Bb) s_cnt[tid] = 0;
    __syncthreads();

    int local = 0;
    for (int i = tid; i < Bb * Ss; i += 256)
        if ((i & 3) != 0 && mask[i] != 0) local = 1;
    if (local) atomicOr(&s_flag, 1);
    __syncthreads();

    bool isU8 = (s_flag != 0);
    int row = tid >> 4, part = tid & 15;
    int cnt = 0;
    if (isU8) {
        const unsigned char* p = mask + row * Ss + part * 128;
        #pragma unroll 4
        for (int e = 0; e < 128; e++) cnt += (p[e] != 0);
    } else {
        const int* p = ((const int*)mask) + row * Ss + part * 128;
        #pragma unroll 4
        for (int e = 0; e < 128; e++) cnt += (p[e] != 0);
    }
    atomicAdd(&s_cnt[row], cnt);
    __syncthreads();
    if (tid < Bb) g_lengths[tid] = s_cnt[tid];
}

// ---------------------------------------------------------------------------
// Prep: fp32 -> bf16 hi/lo for enc, dec; transposed hi/lo for weights.
// ---------------------------------------------------------------------------
__global__ void prep_convert_kernel(const float* __restrict__ enc,
                                    const float* __restrict__ dec,
                                    const float* __restrict__ Wenc,
                                    const float* __restrict__ Wfin)
{
    int tid = blockIdx.x * blockDim.x + threadIdx.x;
    int stride = gridDim.x * blockDim.x;

    const int NE4 = (Bb * Ss * Ee) / 4;
    for (int i = tid; i < NE4; i += stride) {
        float4 v = ((const float4*)enc)[i];
        ushort4 hv, lv;
        bsplit(v.x, hv.x, lv.x); bsplit(v.y, hv.y, lv.y);
        bsplit(v.z, hv.z, lv.z); bsplit(v.w, hv.w, lv.w);
        ((ushort4*)g_encH)[i] = hv;
        ((ushort4*)g_encL)[i] = lv;
    }
    const int ND4 = (Bb * Tt * Dd) / 4;
    for (int i = tid; i < ND4; i += stride) {
        float4 v = ((const float4*)dec)[i];
        ushort4 hv, lv;
        bsplit(v.x, hv.x, lv.x); bsplit(v.y, hv.y, lv.y);
        bsplit(v.z, hv.z, lv.z); bsplit(v.w, hv.w, lv.w);
        ((ushort4*)g_decH)[i] = hv;
        ((ushort4*)g_decL)[i] = lv;
    }
    for (int i = tid; i < 256 * 256; i += stride) {
        int d = i >> 8, e = i & 255;
        unsigned short h, l;
        bsplit(Wenc[e * 256 + d], h, l);
        *(unsigned short*)&g_WencTH[i] = h;
        *(unsigned short*)&g_WencTL[i] = l;
    }
    for (int i = tid; i < 256 * 512; i += stride) {
        int d = i >> 9, f = i & 511;
        unsigned short h, l;
        bsplit(Wfin[f * 256 + d], h, l);
        *(unsigned short*)&g_WfinTH[i] = h;
        *(unsigned short*)&g_WfinTL[i] = l;
    }
}

// ---------------------------------------------------------------------------
// Split-bf16 tensor-core GEMM with ldmatrix fragment loads.
// ---------------------------------------------------------------------------
#define GSM_A_H 0
#define GSM_A_L 18432
#define GSM_B_H 36864
#define GSM_B_L 55296
#define GSM_TOTAL 73728

template<int KTOT, bool TANH>
__global__ __launch_bounds__(256, 2)
void mma_gemm_kernel(const __nv_bfloat16* __restrict__ A1H,
                     const __nv_bfloat16* __restrict__ A1L,
                     const __nv_bfloat16* __restrict__ A2H,
                     const __nv_bfloat16* __restrict__ A2L,
                     const __nv_bfloat16* __restrict__ BTH,
                     const __nv_bfloat16* __restrict__ BTL,
                     float* __restrict__ Cf,
                     __nv_bfloat16* __restrict__ CH,
                     __nv_bfloat16* __restrict__ CL)
{
    extern __shared__ char dyn[];
    __nv_bfloat16* sAH = (__nv_bfloat16*)(dyn + GSM_A_H);
    __nv_bfloat16* sAL = (__nv_bfloat16*)(dyn + GSM_A_L);
    __nv_bfloat16* sBH = (__nv_bfloat16*)(dyn + GSM_B_H);
    __nv_bfloat16* sBL = (__nv_bfloat16*)(dyn + GSM_B_L);
    uint32_t base = smem_u32(dyn);
    uint32_t bAH = base + GSM_A_H, bAL = base + GSM_A_L;
    uint32_t bBH = base + GSM_B_H, bBL = base + GSM_B_L;

    int tid = threadIdx.x, lane = tid & 31, wid = tid >> 5;
    int warpM = wid & 3, warpN = wid >> 2;
    int m0 = blockIdx.y * 128, n0 = blockIdx.x * 128;
    int r = lane >> 2, cc = (lane & 3) * 2;

    float acc[2][8][4];
    #pragma unroll
    for (int i = 0; i < 2; i++)
        #pragma unroll
        for (int j = 0; j < 8; j++)
            #pragma unroll
            for (int q = 0; q < 4; q++) acc[i][j][q] = 0.f;

    for (int kc = 0; kc < KTOT; kc += 64) {
        const __nv_bfloat16* AH = A1H;
        const __nv_bfloat16* AL = A1L;
        int kcol = kc;
        if (KTOT > 256 && kc >= 256) { AH = A2H; AL = A2L; kcol = kc - 256; }

        #pragma unroll
        for (int u = 0; u < 4; u++) {
            int f = tid + u * 256;
            int rr = f >> 3, c8 = f & 7;
            *(uint4*)&sAH[rr * 72 + c8 * 8] =
                *(const uint4*)&AH[(size_t)(m0 + rr) * 256 + kcol + c8 * 8];
            *(uint4*)&sAL[rr * 72 + c8 * 8] =
                *(const uint4*)&AL[(size_t)(m0 + rr) * 256 + kcol + c8 * 8];
            *(uint4*)&sBH[rr * 72 + c8 * 8] =
                *(const uint4*)&BTH[(size_t)(n0 + rr) * KTOT + kc + c8 * 8];
            *(uint4*)&sBL[rr * 72 + c8 * 8] =
                *(const uint4*)&BTL[(size_t)(n0 + rr) * KTOT + kc + c8 * 8];
        }
        __syncthreads();

        #pragma unroll
        for (int ks = 0; ks < 4; ks++) {
            int kb = ks * 32;           // byte offset of k-slice
            uint32_t aH[2][4], aL[2][4];
            #pragma unroll
            for (int mt = 0; mt < 2; mt++) {
                uint32_t ad = ldsm_addr(bAH, 144, warpM * 32 + mt * 16, kb, lane);
                ldsm_x4_nt(aH[mt][0], aH[mt][1], aH[mt][2], aH[mt][3], ad);
                ad = ldsm_addr(bAL, 144, warpM * 32 + mt * 16, kb, lane);
                ldsm_x4_nt(aL[mt][0], aL[mt][1], aL[mt][2], aL[mt][3], ad);
            }
            #pragma unroll
            for (int pr = 0; pr < 4; pr++) {
                int nrow = warpN * 64 + pr * 16;
                uint32_t h0, h1, h2, h3, l0, l1, l2, l3;
                ldsm_x4_nt(h0, h1, h2, h3, ldsm_addr(bBH, 144, nrow, kb, lane));
                ldsm_x4_nt(l0, l1, l2, l3, ldsm_addr(bBL, 144, nrow, kb, lane));
                uint32_t bH0[2] = {h0, h2}, bH1[2] = {h1, h3};
                uint32_t bL0[2] = {l0, l2}, bL1[2] = {l1, l3};
                int nt = pr * 2;
                #pragma unroll
                for (int mt = 0; mt < 2; mt++) {
                    mma16816(acc[mt][nt], aH[mt], bH0);
                    mma16816(acc[mt][nt], aH[mt], bL0);
                    mma16816(acc[mt][nt], aL[mt], bH0);
                    mma16816(acc[mt][nt + 1], aH[mt], bH1);
                    mma16816(acc[mt][nt + 1], aH[mt], bL1);
                    mma16816(acc[mt][nt + 1], aL[mt], bH1);
                }
            }
        }
        __syncthreads();
    }

    #pragma unroll
    for (int mt = 0; mt < 2; mt++) {
        #pragma unroll
        for (int nt = 0; nt < 8; nt++) {
            int m = m0 + warpM * 32 + mt * 16 + r;
            int n = n0 + warpN * 64 + nt * 8 + cc;
            float c0 = acc[mt][nt][0], c1 = acc[mt][nt][1];
            float c2 = acc[mt][nt][2], c3 = acc[mt][nt][3];
            if (TANH) {
                float2 v0 = make_float2(tanhf(c0), tanhf(c1));
                float2 v1 = make_float2(tanhf(c2), tanhf(c3));
                *(float2*)&Cf[(size_t)m * 256 + n] = v0;
                *(float2*)&Cf[(size_t)(m + 8) * 256 + n] = v1;
            } else {
                unsigned short h0, l0, h1, l1, h2, l2, h3, l3;
                bsplit(c0, h0, l0); bsplit(c1, h1, l1);
                bsplit(c2, h2, l2); bsplit(c3, h3, l3);
                *(uint32_t*)&CH[(size_t)m * 256 + n] = pack2(h0, h1);
                *(uint32_t*)&CL[(size_t)m * 256 + n] = pack2(l0, l1);
                *(uint32_t*)&CH[(size_t)(m + 8) * 256 + n] = pack2(h2, h3);
                *(uint32_t*)&CL[(size_t)(m + 8) * 256 + n] = pack2(l2, l3);
            }
        }
    }
}

// ---------------------------------------------------------------------------
// Fused flash attention, split-KV, ldmatrix fragment loads.
// ---------------------------------------------------------------------------
#define ASM_A_H   0
#define ASM_A_L   9216
#define ASM_B_H   18432
#define ASM_B_L   27648
#define ASM_S     36864
#define ASM_ENC_H 54272
#define ASM_ENC_L 71680
#define ASM_M     89088
#define ASM_L     89344
#define ASM_SC    89600
#define ASM_TOTAL 89856

__global__ __launch_bounds__(256, 2)
void attn_kernel()
{
    extern __shared__ char dyn[];
    __nv_bfloat16* sAH = (__nv_bfloat16*)(dyn + ASM_A_H);
    __nv_bfloat16* sAL = (__nv_bfloat16*)(dyn + ASM_A_L);
    __nv_bfloat16* sBH = (__nv_bfloat16*)(dyn + ASM_B_H);
    __nv_bfloat16* sBL = (__nv_bfloat16*)(dyn + ASM_B_L);
    float* sS = (float*)(dyn + ASM_S);
    __nv_bfloat16* sEH = (__nv_bfloat16*)(dyn + ASM_ENC_H);
    __nv_bfloat16* sEL = (__nv_bfloat16*)(dyn + ASM_ENC_L);
    float* mstat = (float*)(dyn + ASM_M);
    float* lstat = (float*)(dyn + ASM_L);
    float* sscale = (float*)(dyn + ASM_SC);

    uint32_t base = smem_u32(dyn);
    uint32_t bAH = base + ASM_A_H, bAL = base + ASM_A_L;
    uint32_t bBH = base + ASM_B_H, bBL = base + ASM_B_L;
    uint32_t encHb = base + ASM_ENC_H, encLb = base + ASM_ENC_L;

    int tid = threadIdx.x, lane = tid & 31, wid = tid >> 5;
    int warpT = wid & 3;
    int warpS = wid >> 2;
    int r = lane >> 2, cc = (lane & 3) * 2;
    int b = blockIdx.y;
    int t0 = blockIdx.x * 64;
    int slice = blockIdx.z;
    int len = g_lengths[b];

    int sbeg = slice * SLICE_S;
    if (sbeg >= len) return;
    int send = min(sbeg + SLICE_S, len);

    if (tid < 64) { mstat[tid] = -1e30f; lstat[tid] = 0.f; }

    float ctx[2][8][4];
    #pragma unroll
    for (int i = 0; i < 2; i++)
        #pragma unroll
        for (int j = 0; j < 8; j++)
            #pragma unroll
            for (int q = 0; q < 4; q++) ctx[i][j][q] = 0.f;
    __syncthreads();

    int rowL = tid >> 2, l4 = tid & 3;
    size_t decBase = ((size_t)b * Tt + t0) * 256;
    size_t encBase = (size_t)b * Ss * 256;

    for (int s0 = sbeg; s0 < send; s0 += 64) {
        // ---------------- score GEMM: 64t x 64s, K=256 in 4 chunks ---------
        float sacc[4][4];
        #pragma unroll
        for (int j = 0; j < 4; j++)
            #pragma unroll
            for (int q = 0; q < 4; q++) sacc[j][q] = 0.f;

        for (int kch = 0; kch < 4; kch++) {
            int kc = kch * 64;
            #pragma unroll
            for (int u = 0; u < 2; u++) {
                int f = tid + u * 256;
                int rr = f >> 3, c8 = f & 7;
                *(uint4*)&sAH[rr * 72 + c8 * 8] =
                    *(const uint4*)&g_decH[decBase + (size_t)rr * 256 + kc + c8 * 8];
                *(uint4*)&sAL[rr * 72 + c8 * 8] =
                    *(const uint4*)&g_decL[decBase + (size_t)rr * 256 + kc + c8 * 8];
                *(uint4*)&sBH[rr * 72 + c8 * 8] =
                    *(const uint4*)&g_projH[encBase + (size_t)(s0 + rr) * 256 + kc + c8 * 8];
                *(uint4*)&sBL[rr * 72 + c8 * 8] =
                    *(const uint4*)&g_projL[encBase + (size_t)(s0 + rr) * 256 + kc + c8 * 8];
            }
            __syncthreads();

            #pragma unroll
            for (int ks = 0; ks < 4; ks++) {
                int kb = ks * 32;
                uint32_t aH[4], aL[4];
                ldsm_x4_nt(aH[0], aH[1], aH[2], aH[3],
                           ldsm_addr(bAH, 144, warpT * 16, kb, lane));
                ldsm_x4_nt(aL[0], aL[1], aL[2], aL[3],
                           ldsm_addr(bAL, 144, warpT * 16, kb, lane));
                #pragma unroll
                for (int pr = 0; pr < 2; pr++) {
                    int srow = warpS * 32 + pr * 16;
                    uint32_t h0, h1, h2, h3, l0, l1, l2, l3;
                    ldsm_x4_nt(h0, h1, h2, h3,
                               ldsm_addr(bBH, 144, srow, kb, lane));
                    ldsm_x4_nt(l0, l1, l2, l3,
                               ldsm_addr(bBL, 144, srow, kb, lane));
                    uint32_t bH0[2] = {h0, h2}, bH1[2] = {h1, h3};
                    uint32_t bL0[2] = {l0, l2}, bL1[2] = {l1, l3};
                    int nt = pr * 2;
                    mma16816(sacc[nt], aH, bH0);
                    mma16816(sacc[nt], aH, bL0);
                    mma16816(sacc[nt], aL, bH0);
                    mma16816(sacc[nt + 1], aH, bH1);
                    mma16816(sacc[nt + 1], aH, bL1);
                    mma16816(sacc[nt + 1], aL, bH1);
                }
            }
            __syncthreads();
        }

        #pragma unroll
        for (int nt = 0; nt < 4; nt++) {
            int tr = warpT * 16 + r;
            int sc = warpS * 32 + nt * 8 + cc;
            *(float2*)&sS[tr * 68 + sc] = make_float2(sacc[nt][0], sacc[nt][1]);
            *(float2*)&sS[(tr + 8) * 68 + sc] = make_float2(sacc[nt][2], sacc[nt][3]);
        }
        __syncthreads();

        // ---------------- online softmax -----------------------------------
        float v[16];
        float tmax = -1e30f;
        int sbase = l4 * 16;
        #pragma unroll
        for (int q = 0; q < 16; q++) {
            int sc = sbase + q;
            float val = (s0 + sc < len) ? sS[rowL * 68 + sc] : -1e30f;
            v[q] = val;
            tmax = fmaxf(tmax, val);
        }
        tmax = fmaxf(tmax, __shfl_xor_sync(0xffffffffu, tmax, 1));
        tmax = fmaxf(tmax, __shfl_xor_sync(0xffffffffu, tmax, 2));
        float mOld = mstat[rowL];
        float mNew = fmaxf(mOld, tmax);
        float sum = 0.f;
        #pragma unroll
        for (int q = 0; q < 16; q++) {
            v[q] = __expf(v[q] - mNew);
            sum += v[q];
        }
        sum += __shfl_xor_sync(0xffffffffu, sum, 1);
        sum += __shfl_xor_sync(0xffffffffu, sum, 2);
        float scl = __expf(mOld - mNew);
        if (l4 == 0) {
            mstat[rowL] = mNew;
            lstat[rowL] = lstat[rowL] * scl + sum;
            sscale[rowL] = scl;
        }
        #pragma unroll
        for (int q = 0; q < 16; q++) {
            unsigned short h, l;
            bsplit(v[q], h, l);
            *(unsigned short*)&sAH[rowL * 72 + sbase + q] = h;
            *(unsigned short*)&sAL[rowL * 72 + sbase + q] = l;
        }
        __syncthreads();

        float f0 = sscale[warpT * 16 + r];
        float f1 = sscale[warpT * 16 + r + 8];
        #pragma unroll
        for (int i = 0; i < 2; i++)
            #pragma unroll
            for (int j = 0; j < 8; j++) {
                ctx[i][j][0] *= f0; ctx[i][j][1] *= f0;
                ctx[i][j][2] *= f1; ctx[i][j][3] *= f1;
            }

        // ---------------- context GEMM: ctx += p @ enc ---------------------
        #pragma unroll
        for (int ec = 0; ec < 2; ec++) {
            #pragma unroll
            for (int u = 0; u < 4; u++) {
                int f = tid + u * 256;
                int rr = f >> 4, c8 = f & 15;
                *(uint4*)&sEH[rr * 136 + c8 * 8] =
                    *(const uint4*)&g_encH[encBase + (size_t)(s0 + rr) * 256 + ec * 128 + c8 * 8];
                *(uint4*)&sEL[rr * 136 + c8 * 8] =
                    *(const uint4*)&g_encL[encBase + (size_t)(s0 + rr) * 256 + ec * 128 + c8 * 8];
            }
            __syncthreads();

            #pragma unroll
            for (int ks = 0; ks < 4; ks++) {
                int kb = ks * 32;
                uint32_t aH[4], aL[4];
                ldsm_x4_nt(aH[0], aH[1], aH[2], aH[3],
                           ldsm_addr(bAH, 144, warpT * 16, kb, lane));
                ldsm_x4_nt(aL[0], aL[1], aL[2], aL[3],
                           ldsm_addr(bAL, 144, warpT * 16, kb, lane));
                uint32_t lrow = (uint32_t)(ks * 16 + (lane & 15));
                uint32_t lcol0 = (uint32_t)(warpS * 64 + ((lane >> 4) << 3));
                #pragma unroll
                for (int pair = 0; pair < 4; pair++) {
                    uint32_t off = (lrow * 136 + lcol0 + pair * 16) * 2;
                    uint32_t bh0, bh1, bh2, bh3, bl0, bl1, bl2, bl3;
                    ldsm_x4_t(bh0, bh1, bh2, bh3, encHb + off);
                    ldsm_x4_t(bl0, bl1, bl2, bl3, encLb + off);
                    uint32_t bH0[2] = {bh0, bh1}, bH1[2] = {bh2, bh3};
                    uint32_t bL0[2] = {bl0, bl1}, bL1[2] = {bl2, bl3};
                    int nt = pair * 2;
                    mma16816(ctx[ec][nt], aH, bH0);
                    mma16816(ctx[ec][nt], aH, bL0);
                    mma16816(ctx[ec][nt], aL, bH0);
                    mma16816(ctx[ec][nt + 1], aH, bH1);
                    mma16816(ctx[ec][nt + 1], aH, bL1);
                    mma16816(ctx[ec][nt + 1], aL, bH1);
                }
            }
            __syncthreads();
        }
    }

    // ---------------- write partial (m, l, unnormalized ctx) ----------------
    size_t pmBase = (((size_t)slice * Bb + b) * Tt) + t0;
    if (tid < 64) {
        g_pm[pmBase + tid] = mstat[tid];
        g_pl[pmBase + tid] = lstat[tid];
    }
    int t = t0 + warpT * 16 + r;
    size_t obase = (((size_t)slice * Bb + b) * Tt + t) * 256;
    #pragma unroll
    for (int ec = 0; ec < 2; ec++) {
        #pragma unroll
        for (int nt = 0; nt < 8; nt++) {
            int e = ec * 128 + warpS * 64 + nt * 8 + cc;
            *(float2*)&g_pctx[obase + e] =
                make_float2(ctx[ec][nt][0], ctx[ec][nt][1]);
            *(float2*)&g_pctx[obase + 8 * 256 + e] =
                make_float2(ctx[ec][nt][2], ctx[ec][nt][3]);
        }
    }
}

// ---------------------------------------------------------------------------
// Combine: merge slice partials -> normalized ctx, split to bf16 hi/lo.
// ---------------------------------------------------------------------------
__global__ __launch_bounds__(256)
void combine_kernel()
{
    __shared__ float w[64][4];
    int tid = threadIdx.x;
    int b = blockIdx.y;
    int t0 = blockIdx.x * 64;
    int len = g_lengths[b];
    int nsl = min(NSLICE, (len + SLICE_S - 1) / SLICE_S);

    if (tid < 64) {
        int t = t0 + tid;
        float mv[4], lv[4];
        float M = -1e30f;
        for (int s = 0; s < nsl; s++) {
            size_t off = (((size_t)s * Bb + b) * Tt) + t;
            mv[s] = g_pm[off];
            lv[s] = g_pl[off];
            M = fmaxf(M, mv[s]);
        }
        float L = 0.f;
        float ws[4];
        for (int s = 0; s < nsl; s++) {
            float e = __expf(mv[s] - M);
            ws[s] = e;
            L += e * lv[s];
        }
        float inv = 1.0f / L;
        for (int s = 0; s < 4; s++)
            w[tid][s] = (s < nsl) ? ws[s] * inv : 0.f;
    }
    __syncthreads();

    int r = tid >> 2, c0 = (tid & 3) * 64;
    int t = t0 + r;
    float wr[4] = {w[r][0], w[r][1], w[r][2], w[r][3]};
    size_t eBase = (((size_t)b) * Tt + t) * 256 + c0;
    #pragma unroll 4
    for (int e = 0; e < 64; e += 4) {
        float4 acc = make_float4(0.f, 0.f, 0.f, 0.f);
        for (int s = 0; s < nsl; s++) {
            size_t off = (((size_t)s * Bb + b) * Tt + t) * 256 + c0 + e;
            float4 v = *(const float4*)&g_pctx[off];
            acc.x += wr[s] * v.x; acc.y += wr[s] * v.y;
            acc.z += wr[s] * v.z; acc.w += wr[s] * v.w;
        }
        unsigned short h0, l0, h1, l1, h2, l2, h3, l3;
        bsplit(acc.x, h0, l0); bsplit(acc.y, h1, l1);
        bsplit(acc.z, h2, l2); bsplit(acc.w, h3, l3);
        *(uint32_t*)&g_ctxH[eBase + e] = pack2(h0, h1);
        *(uint32_t*)&g_ctxH[eBase + e + 2] = pack2(h2, h3);
        *(uint32_t*)&g_ctxL[eBase + e] = pack2(l0, l1);
        *(uint32_t*)&g_ctxL[eBase + e + 2] = pack2(l2, l3);
    }
}

// ---------------------------------------------------------------------------
extern "C" void kernel_launch(void* const* d_in, const int* in_sizes, int n_in,
                              void* d_out, int out_size)
{
    (void)in_sizes; (void)n_in; (void)out_size;
    const float* enc = (const float*)d_in[0];
    const float* dec = (const float*)d_in[1];
    const unsigned char* mask = (const unsigned char*)d_in[2];
    const float* W_enc = (const float*)d_in[3];
    const float* W_fin = (const float*)d_in[4];
    float* out = (float*)d_out;

    void *pEncH, *pEncL, *pDecH, *pDecL, *pProjH, *pProjL;
    void *pCtxH, *pCtxL, *pWeH, *pWeL, *pWfH, *pWfL;
    cudaGetSymbolAddress(&pEncH, g_encH);
    cudaGetSymbolAddress(&pEncL, g_encL);
    cudaGetSymbolAddress(&pDecH, g_decH);
    cudaGetSymbolAddress(&pDecL, g_decL);
    cudaGetSymbolAddress(&pProjH, g_projH);
    cudaGetSymbolAddress(&pProjL, g_projL);
    cudaGetSymbolAddress(&pCtxH, g_ctxH);
    cudaGetSymbolAddress(&pCtxL, g_ctxL);
    cudaGetSymbolAddress(&pWeH, g_WencTH);
    cudaGetSymbolAddress(&pWeL, g_WencTL);
    cudaGetSymbolAddress(&pWfH, g_WfinTH);
    cudaGetSymbolAddress(&pWfL, g_WfinTL);

    cudaFuncSetAttribute((const void*)mma_gemm_kernel<256, false>,
                         cudaFuncAttributeMaxDynamicSharedMemorySize, GSM_TOTAL);
    cudaFuncSetAttribute((const void*)mma_gemm_kernel<512, true>,
                         cudaFuncAttributeMaxDynamicSharedMemorySize, GSM_TOTAL);
    cudaFuncSetAttribute((const void*)attn_kernel,
                         cudaFuncAttributeMaxDynamicSharedMemorySize, ASM_TOTAL);

    detect_lengths_kernel<<<1, 256>>>(mask);
    prep_convert_kernel<<<1024, 256>>>(enc, dec, W_enc, W_fin);

    dim3 g1(2, 256);
    mma_gemm_kernel<256, false><<<g1, 256, GSM_TOTAL>>>(
        (const __nv_bfloat16*)pEncH, (const __nv_bfloat16*)pEncL,
        nullptr, nullptr,
        (const __nv_bfloat16*)pWeH, (const __nv_bfloat16*)pWeL,
        nullptr, (__nv_bfloat16*)pProjH, (__nv_bfloat16*)pProjL);

    dim3 g2(Tt / 64, Bb, NSLICE);
    attn_kernel<<<g2, 256, ASM_TOTAL>>>();

    dim3 gc(Tt / 64, Bb);
    combine_kernel<<<gc, 256>>>();

    dim3 g3(2, 128);
    mma_gemm_kernel<512, true><<<g3, 256, GSM_TOTAL>>>(
        (const __nv_bfloat16*)pCtxH, (const __nv_bfloat16*)pCtxL,
        (const __nv_bfloat16*)pDecH, (const __nv_bfloat16*)pDecL,
        (const __nv_bfloat16*)pWfH, (const __nv_bfloat16*)pWfL,
        out, nullptr, nullptr);
}

// round 6
// speedup vs baseline: 1.1292x; 1.1292x over previous
#include <cuda_runtime.h>
#include <cuda_bf16.h>
#include <math.h>
#include <stdint.h>

#define Bb 16
#define Ss 2048
#define Tt 1024
#define Ee 256
#define Dd 256
#define NSLICE 4
#define SLICE_S 512

// ---------------------------------------------------------------------------
// Scratch (allocation-free: device globals). bf16 hi/lo split representations.
// ---------------------------------------------------------------------------
__device__ __nv_bfloat16 g_encH[Bb * Ss * Ee];
__device__ __nv_bfloat16 g_encL[Bb * Ss * Ee];
__device__ __nv_bfloat16 g_decH[Bb * Tt * Dd];
__device__ __nv_bfloat16 g_decL[Bb * Tt * Dd];
__device__ __nv_bfloat16 g_projH[Bb * Ss * Dd];
__device__ __nv_bfloat16 g_projL[Bb * Ss * Dd];
__device__ __nv_bfloat16 g_ctxH[Bb * Tt * Ee];
__device__ __nv_bfloat16 g_ctxL[Bb * Tt * Ee];
__device__ __nv_bfloat16 g_WencTH[Dd * Ee];
__device__ __nv_bfloat16 g_WencTL[Dd * Ee];
__device__ __nv_bfloat16 g_WfinTH[Dd * (Ee + Dd)];
__device__ __nv_bfloat16 g_WfinTL[Dd * (Ee + Dd)];
__device__ int g_lengths[Bb];
__device__ float g_pctx[NSLICE * Bb * Tt * Ee];
__device__ float g_pm[NSLICE * Bb * Tt];
__device__ float g_pl[NSLICE * Bb * Tt];

// ---------------------------------------------------------------------------
// Helpers
// ---------------------------------------------------------------------------
__device__ __forceinline__ uint32_t smem_u32(const void* p) {
    uint32_t a;
    asm("{ .reg .u64 t; cvta.to.shared.u64 t, %1; cvt.u32.u64 %0, t; }"
        : "=r"(a) : "l"(p));
    return a;
}

__device__ __forceinline__ void mma16816(float* d, const uint32_t* a,
                                         const uint32_t* b) {
    asm volatile(
        "mma.sync.aligned.m16n8k16.row.col.f32.bf16.bf16.f32 "
        "{%0,%1,%2,%3}, {%4,%5,%6,%7}, {%8,%9}, {%0,%1,%2,%3};"
        : "+f"(d[0]), "+f"(d[1]), "+f"(d[2]), "+f"(d[3])
        : "r"(a[0]), "r"(a[1]), "r"(a[2]), "r"(a[3]), "r"(b[0]), "r"(b[1]));
}

__device__ __forceinline__ void ldsm_x4_t(uint32_t& r0, uint32_t& r1,
                                          uint32_t& r2, uint32_t& r3,
                                          uint32_t addr) {
    asm volatile("ldmatrix.sync.aligned.m8n8.x4.trans.shared.b16 "
                 "{%0,%1,%2,%3}, [%4];"
                 : "=r"(r0), "=r"(r1), "=r"(r2), "=r"(r3) : "r"(addr));
}

__device__ __forceinline__ void cp16(uint32_t dst, const void* src) {
    asm volatile("cp.async.cg.shared.global [%0], [%1], 16;"
                 :: "r"(dst), "l"(src));
}
#define CP_COMMIT() asm volatile("cp.async.commit_group;")
#define CP_WAIT(N)  asm volatile("cp.async.wait_group %0;" :: "n"(N))

__device__ __forceinline__ void bsplit(float x, unsigned short& h,
                                       unsigned short& l) {
    __nv_bfloat16 hb = __float2bfloat16(x);
    __nv_bfloat16 lb = __float2bfloat16(x - __bfloat162float(hb));
    h = *(unsigned short*)&hb;
    l = *(unsigned short*)&lb;
}

__device__ __forceinline__ uint32_t pack2(unsigned short a, unsigned short b) {
    return (uint32_t)a | ((uint32_t)b << 16);
}

// ---------------------------------------------------------------------------
// Mask prologue (handles uint8 or int32 bool encodings)
// ---------------------------------------------------------------------------
__global__ void detect_lengths_kernel(const unsigned char* __restrict__ mask)
{
    __shared__ int s_flag;
    __shared__ int s_cnt[Bb];
    int tid = threadIdx.x;
    if (tid == 0) s_flag = 0;
    if (tid < Bb) s_cnt[tid] = 0;
    __syncthreads();

    int local = 0;
    for (int i = tid; i < Bb * Ss; i += 256)
        if ((i & 3) != 0 && mask[i] != 0) local = 1;
    if (local) atomicOr(&s_flag, 1);
    __syncthreads();

    bool isU8 = (s_flag != 0);
    int row = tid >> 4, part = tid & 15;
    int cnt = 0;
    if (isU8) {
        const unsigned char* p = mask + row * Ss + part * 128;
        #pragma unroll 4
        for (int e = 0; e < 128; e++) cnt += (p[e] != 0);
    } else {
        const int* p = ((const int*)mask) + row * Ss + part * 128;
        #pragma unroll 4
        for (int e = 0; e < 128; e++) cnt += (p[e] != 0);
    }
    atomicAdd(&s_cnt[row], cnt);
    __syncthreads();
    if (tid < Bb) g_lengths[tid] = s_cnt[tid];
}

// ---------------------------------------------------------------------------
// Prep: fp32 -> bf16 hi/lo for enc, dec; transposed hi/lo for weights.
// ---------------------------------------------------------------------------
__global__ void prep_convert_kernel(const float* __restrict__ enc,
                                    const float* __restrict__ dec,
                                    const float* __restrict__ Wenc,
                                    const float* __restrict__ Wfin)
{
    int tid = blockIdx.x * blockDim.x + threadIdx.x;
    int stride = gridDim.x * blockDim.x;

    const int NE4 = (Bb * Ss * Ee) / 4;
    for (int i = tid; i < NE4; i += stride) {
        float4 v = ((const float4*)enc)[i];
        ushort4 hv, lv;
        bsplit(v.x, hv.x, lv.x); bsplit(v.y, hv.y, lv.y);
        bsplit(v.z, hv.z, lv.z); bsplit(v.w, hv.w, lv.w);
        ((ushort4*)g_encH)[i] = hv;
        ((ushort4*)g_encL)[i] = lv;
    }
    const int ND4 = (Bb * Tt * Dd) / 4;
    for (int i = tid; i < ND4; i += stride) {
        float4 v = ((const float4*)dec)[i];
        ushort4 hv, lv;
        bsplit(v.x, hv.x, lv.x); bsplit(v.y, hv.y, lv.y);
        bsplit(v.z, hv.z, lv.z); bsplit(v.w, hv.w, lv.w);
        ((ushort4*)g_decH)[i] = hv;
        ((ushort4*)g_decL)[i] = lv;
    }
    for (int i = tid; i < 256 * 256; i += stride) {
        int d = i >> 8, e = i & 255;
        unsigned short h, l;
        bsplit(Wenc[e * 256 + d], h, l);
        *(unsigned short*)&g_WencTH[i] = h;
        *(unsigned short*)&g_WencTL[i] = l;
    }
    for (int i = tid; i < 256 * 512; i += stride) {
        int d = i >> 9, f = i & 511;
        unsigned short h, l;
        bsplit(Wfin[f * 256 + d], h, l);
        *(unsigned short*)&g_WfinTH[i] = h;
        *(unsigned short*)&g_WfinTL[i] = l;
    }
}

// ---------------------------------------------------------------------------
// Split-bf16 tensor-core GEMM (round-4 proven version)
// ---------------------------------------------------------------------------
#define GSM_A_H 0
#define GSM_A_L 18432
#define GSM_B_H 36864
#define GSM_B_L 55296
#define GSM_TOTAL 73728

template<int KTOT, bool TANH>
__global__ __launch_bounds__(256, 2)
void mma_gemm_kernel(const __nv_bfloat16* __restrict__ A1H,
                     const __nv_bfloat16* __restrict__ A1L,
                     const __nv_bfloat16* __restrict__ A2H,
                     const __nv_bfloat16* __restrict__ A2L,
                     const __nv_bfloat16* __restrict__ BTH,
                     const __nv_bfloat16* __restrict__ BTL,
                     float* __restrict__ Cf,
                     __nv_bfloat16* __restrict__ CH,
                     __nv_bfloat16* __restrict__ CL)
{
    extern __shared__ char dyn[];
    __nv_bfloat16* sAH = (__nv_bfloat16*)(dyn + GSM_A_H);
    __nv_bfloat16* sAL = (__nv_bfloat16*)(dyn + GSM_A_L);
    __nv_bfloat16* sBH = (__nv_bfloat16*)(dyn + GSM_B_H);
    __nv_bfloat16* sBL = (__nv_bfloat16*)(dyn + GSM_B_L);

    int tid = threadIdx.x, lane = tid & 31, wid = tid >> 5;
    int warpM = wid & 3, warpN = wid >> 2;
    int m0 = blockIdx.y * 128, n0 = blockIdx.x * 128;
    int r = lane >> 2, cc = (lane & 3) * 2;

    float acc[2][8][4];
    #pragma unroll
    for (int i = 0; i < 2; i++)
        #pragma unroll
        for (int j = 0; j < 8; j++)
            #pragma unroll
            for (int q = 0; q < 4; q++) acc[i][j][q] = 0.f;

    for (int kc = 0; kc < KTOT; kc += 64) {
        const __nv_bfloat16* AH = A1H;
        const __nv_bfloat16* AL = A1L;
        int kcol = kc;
        if (KTOT > 256 && kc >= 256) { AH = A2H; AL = A2L; kcol = kc - 256; }

        #pragma unroll
        for (int u = 0; u < 4; u++) {
            int f = tid + u * 256;
            int rr = f >> 3, c8 = f & 7;
            *(uint4*)&sAH[rr * 72 + c8 * 8] =
                *(const uint4*)&AH[(size_t)(m0 + rr) * 256 + kcol + c8 * 8];
            *(uint4*)&sAL[rr * 72 + c8 * 8] =
                *(const uint4*)&AL[(size_t)(m0 + rr) * 256 + kcol + c8 * 8];
            *(uint4*)&sBH[rr * 72 + c8 * 8] =
                *(const uint4*)&BTH[(size_t)(n0 + rr) * KTOT + kc + c8 * 8];
            *(uint4*)&sBL[rr * 72 + c8 * 8] =
                *(const uint4*)&BTL[(size_t)(n0 + rr) * KTOT + kc + c8 * 8];
        }
        __syncthreads();

        #pragma unroll
        for (int ks = 0; ks < 4; ks++) {
            int k0 = ks * 16;
            uint32_t aH[2][4], aL[2][4];
            #pragma unroll
            for (int mt = 0; mt < 2; mt++) {
                int ar = warpM * 32 + mt * 16 + r;
                int ac = k0 + cc;
                aH[mt][0] = *(uint32_t*)&sAH[ar * 72 + ac];
                aH[mt][1] = *(uint32_t*)&sAH[(ar + 8) * 72 + ac];
                aH[mt][2] = *(uint32_t*)&sAH[ar * 72 + ac + 8];
                aH[mt][3] = *(uint32_t*)&sAH[(ar + 8) * 72 + ac + 8];
                aL[mt][0] = *(uint32_t*)&sAL[ar * 72 + ac];
                aL[mt][1] = *(uint32_t*)&sAL[(ar + 8) * 72 + ac];
                aL[mt][2] = *(uint32_t*)&sAL[ar * 72 + ac + 8];
                aL[mt][3] = *(uint32_t*)&sAL[(ar + 8) * 72 + ac + 8];
            }
            #pragma unroll
            for (int nt = 0; nt < 8; nt++) {
                int bn = warpN * 64 + nt * 8 + r;
                int bc = k0 + cc;
                uint32_t bH[2], bL[2];
                bH[0] = *(uint32_t*)&sBH[bn * 72 + bc];
                bH[1] = *(uint32_t*)&sBH[bn * 72 + bc + 8];
                bL[0] = *(uint32_t*)&sBL[bn * 72 + bc];
                bL[1] = *(uint32_t*)&sBL[bn * 72 + bc + 8];
                #pragma unroll
                for (int mt = 0; mt < 2; mt++) {
                    mma16816(acc[mt][nt], aH[mt], bH);
                    mma16816(acc[mt][nt], aH[mt], bL);
                    mma16816(acc[mt][nt], aL[mt], bH);
                }
            }
        }
        __syncthreads();
    }

    #pragma unroll
    for (int mt = 0; mt < 2; mt++) {
        #pragma unroll
        for (int nt = 0; nt < 8; nt++) {
            int m = m0 + warpM * 32 + mt * 16 + r;
            int n = n0 + warpN * 64 + nt * 8 + cc;
            float c0 = acc[mt][nt][0], c1 = acc[mt][nt][1];
            float c2 = acc[mt][nt][2], c3 = acc[mt][nt][3];
            if (TANH) {
                float2 v0 = make_float2(tanhf(c0), tanhf(c1));
                float2 v1 = make_float2(tanhf(c2), tanhf(c3));
                *(float2*)&Cf[(size_t)m * 256 + n] = v0;
                *(float2*)&Cf[(size_t)(m + 8) * 256 + n] = v1;
            } else {
                unsigned short h0, l0, h1, l1, h2, l2, h3, l3;
                bsplit(c0, h0, l0); bsplit(c1, h1, l1);
                bsplit(c2, h2, l2); bsplit(c3, h3, l3);
                *(uint32_t*)&CH[(size_t)m * 256 + n] = pack2(h0, h1);
                *(uint32_t*)&CL[(size_t)m * 256 + n] = pack2(l0, l1);
                *(uint32_t*)&CH[(size_t)(m + 8) * 256 + n] = pack2(h2, h3);
                *(uint32_t*)&CL[(size_t)(m + 8) * 256 + n] = pack2(l2, l3);
            }
        }
    }
}

// ---------------------------------------------------------------------------
// Fused flash attention, split-KV, cp.async double-buffered, register softmax.
// smem layout (bytes):
//   A bufs (dec 64x72 hi+lo) x2 : 0 / 9216 / 18432 / 27648
//   B bufs (proj)            x2 : 36864 / 46080 / 55296 / 64512
//   enc (64x136 hi+lo)           : 73728 / 91136
//   partials pmax/psum 128 f ea  : 108544 / 109056
// p tiles (softmax output) reuse A-buf1 (chunk3's dec, dead after scores).
// ---------------------------------------------------------------------------
#define O_AH0 0
#define O_AL0 9216
#define O_AH1 18432
#define O_AL1 27648
#define O_BH0 36864
#define O_BL0 46080
#define O_BH1 55296
#define O_BL1 64512
#define O_EH  73728
#define O_EL  91136
#define O_PMAX 108544
#define O_PSUM 109056
#define A_TOTAL 109568

__device__ __forceinline__ void stage_score_chunk(uint32_t base, int sel,
                                                  size_t decBase, size_t encBase,
                                                  int s0, int kc, int tid)
{
    uint32_t ah = base + (sel ? O_AH1 : O_AH0);
    uint32_t al = base + (sel ? O_AL1 : O_AL0);
    uint32_t bh = base + (sel ? O_BH1 : O_BH0);
    uint32_t bl = base + (sel ? O_BL1 : O_BL0);
    #pragma unroll
    for (int u = 0; u < 2; u++) {
        int f = tid + u * 256;
        int rr = f >> 3, c = f & 7;
        uint32_t doff = rr * 144 + c * 16;
        size_t ga = decBase + (size_t)rr * 256 + kc + c * 8;
        size_t gb = encBase + (size_t)(s0 + rr) * 256 + kc + c * 8;
        cp16(ah + doff, g_decH + ga);
        cp16(al + doff, g_decL + ga);
        cp16(bh + doff, g_projH + gb);
        cp16(bl + doff, g_projL + gb);
    }
}

__device__ __forceinline__ void stage_enc_chunk(uint32_t base, size_t encBase,
                                                int s0, int ec, int tid)
{
    uint32_t eh = base + O_EH, el = base + O_EL;
    #pragma unroll
    for (int u = 0; u < 4; u++) {
        int f = tid + u * 256;
        int rr = f >> 4, c = f & 15;
        uint32_t doff = rr * 272 + c * 16;
        size_t g = encBase + (size_t)(s0 + rr) * 256 + ec * 128 + c * 8;
        cp16(eh + doff, g_encH + g);
        cp16(el + doff, g_encL + g);
    }
}

__global__ __launch_bounds__(256, 2)
void attn_kernel()
{
    extern __shared__ char dyn[];
    uint32_t base = smem_u32(dyn);
    float* sPmax = (float*)(dyn + O_PMAX);
    float* sPsum = (float*)(dyn + O_PSUM);
    __nv_bfloat16* pH = (__nv_bfloat16*)(dyn + O_AH1);
    __nv_bfloat16* pL = (__nv_bfloat16*)(dyn + O_AL1);
    uint32_t encHb = base + O_EH, encLb = base + O_EL;

    int tid = threadIdx.x, lane = tid & 31, wid = tid >> 5;
    int warpT = wid & 3;
    int warpS = wid >> 2;
    int r = lane >> 2, cc = (lane & 3) * 2;
    int b = blockIdx.y;
    int t0 = blockIdx.x * 64;
    int slice = blockIdx.z;
    int len = g_lengths[b];

    int sbeg = slice * SLICE_S;
    if (sbeg >= len) return;
    int send = min(sbeg + SLICE_S, len);

    size_t decBase = ((size_t)b * Tt + t0) * 256;
    size_t encBase = (size_t)b * Ss * 256;

    int row0 = warpT * 16 + r;
    int row1 = row0 + 8;
    float mreg0 = -1e30f, mreg1 = -1e30f;
    float lreg0 = 0.f, lreg1 = 0.f;

    float ctx[2][8][4];
    #pragma unroll
    for (int i = 0; i < 2; i++)
        #pragma unroll
        for (int j = 0; j < 8; j++)
            #pragma unroll
            for (int q = 0; q < 4; q++) ctx[i][j][q] = 0.f;

    // prologue prefetch: chunk0 then enc0 (order matters for wait counting)
    stage_score_chunk(base, 0, decBase, encBase, sbeg, 0, tid);
    CP_COMMIT();
    stage_enc_chunk(base, encBase, sbeg, 0, tid);
    CP_COMMIT();

    for (int s0 = sbeg; s0 < send; s0 += 64) {
        bool have_next = (s0 + 64 < send);

        // ---------------- score GEMM: 64t x 64s, K=256 in 4 chunks ---------
        float sacc[4][4];
        #pragma unroll
        for (int j = 0; j < 4; j++)
            #pragma unroll
            for (int q = 0; q < 4; q++) sacc[j][q] = 0.f;

        #pragma unroll
        for (int kch = 0; kch < 4; kch++) {
            if (kch < 3) {
                stage_score_chunk(base, (kch + 1) & 1, decBase, encBase,
                                  s0, (kch + 1) * 64, tid);
                CP_COMMIT();
            }
            if (kch == 0)      { CP_WAIT(2); }
            else if (kch == 3) { CP_WAIT(0); }
            else               { CP_WAIT(1); }
            __syncthreads();
            if (kch == 3 && have_next) {
                // buffers 0 free (last used by chunk2); prefetch next tile c0
                stage_score_chunk(base, 0, decBase, encBase, s0 + 64, 0, tid);
                CP_COMMIT();
            }

            int sel = kch & 1;
            const __nv_bfloat16* sAH =
                (const __nv_bfloat16*)(dyn + (sel ? O_AH1 : O_AH0));
            const __nv_bfloat16* sAL =
                (const __nv_bfloat16*)(dyn + (sel ? O_AL1 : O_AL0));
            const __nv_bfloat16* sBH =
                (const __nv_bfloat16*)(dyn + (sel ? O_BH1 : O_BH0));
            const __nv_bfloat16* sBL =
                (const __nv_bfloat16*)(dyn + (sel ? O_BL1 : O_BL0));

            #pragma unroll
            for (int ks = 0; ks < 4; ks++) {
                int k0 = ks * 16;
                int ar = warpT * 16 + r;
                int ac = k0 + cc;
                uint32_t aH[4], aL[4];
                aH[0] = *(uint32_t*)&sAH[ar * 72 + ac];
                aH[1] = *(uint32_t*)&sAH[(ar + 8) * 72 + ac];
                aH[2] = *(uint32_t*)&sAH[ar * 72 + ac + 8];
                aH[3] = *(uint32_t*)&sAH[(ar + 8) * 72 + ac + 8];
                aL[0] = *(uint32_t*)&sAL[ar * 72 + ac];
                aL[1] = *(uint32_t*)&sAL[(ar + 8) * 72 + ac];
                aL[2] = *(uint32_t*)&sAL[ar * 72 + ac + 8];
                aL[3] = *(uint32_t*)&sAL[(ar + 8) * 72 + ac + 8];
                #pragma unroll
                for (int nt = 0; nt < 4; nt++) {
                    int bn = warpS * 32 + nt * 8 + r;
                    uint32_t bH[2], bL[2];
                    bH[0] = *(uint32_t*)&sBH[bn * 72 + ac];
                    bH[1] = *(uint32_t*)&sBH[bn * 72 + ac + 8];
                    bL[0] = *(uint32_t*)&sBL[bn * 72 + ac];
                    bL[1] = *(uint32_t*)&sBL[bn * 72 + ac + 8];
                    mma16816(sacc[nt], aH, bH);
                    mma16816(sacc[nt], aH, bL);
                    mma16816(sacc[nt], aL, bH);
                }
            }
            __syncthreads();
        }

        // ---------------- register softmax ---------------------------------
        float rm0 = -1e30f, rm1 = -1e30f;
        #pragma unroll
        for (int nt = 0; nt < 4; nt++) {
            int cg = s0 + warpS * 32 + nt * 8 + cc;
            if (cg >= len)     { sacc[nt][0] = -1e30f; sacc[nt][2] = -1e30f; }
            if (cg + 1 >= len) { sacc[nt][1] = -1e30f; sacc[nt][3] = -1e30f; }
            rm0 = fmaxf(rm0, fmaxf(sacc[nt][0], sacc[nt][1]));
            rm1 = fmaxf(rm1, fmaxf(sacc[nt][2], sacc[nt][3]));
        }
        rm0 = fmaxf(rm0, __shfl_xor_sync(0xffffffffu, rm0, 1));
        rm0 = fmaxf(rm0, __shfl_xor_sync(0xffffffffu, rm0, 2));
        rm1 = fmaxf(rm1, __shfl_xor_sync(0xffffffffu, rm1, 1));
        rm1 = fmaxf(rm1, __shfl_xor_sync(0xffffffffu, rm1, 2));
        if ((lane & 3) == 0) {
            sPmax[row0 * 2 + warpS] = rm0;
            sPmax[row1 * 2 + warpS] = rm1;
        }
        __syncthreads();

        float mN0 = fmaxf(mreg0, fmaxf(sPmax[row0 * 2], sPmax[row0 * 2 + 1]));
        float mN1 = fmaxf(mreg1, fmaxf(sPmax[row1 * 2], sPmax[row1 * 2 + 1]));
        float scl0 = __expf(mreg0 - mN0);
        float scl1 = __expf(mreg1 - mN1);
        mreg0 = mN0; mreg1 = mN1;

        float sum0 = 0.f, sum1 = 0.f;
        #pragma unroll
        for (int nt = 0; nt < 4; nt++) {
            sacc[nt][0] = __expf(sacc[nt][0] - mN0);
            sacc[nt][1] = __expf(sacc[nt][1] - mN0);
            sacc[nt][2] = __expf(sacc[nt][2] - mN1);
            sacc[nt][3] = __expf(sacc[nt][3] - mN1);
            sum0 += sacc[nt][0] + sacc[nt][1];
            sum1 += sacc[nt][2] + sacc[nt][3];
        }
        sum0 += __shfl_xor_sync(0xffffffffu, sum0, 1);
        sum0 += __shfl_xor_sync(0xffffffffu, sum0, 2);
        sum1 += __shfl_xor_sync(0xffffffffu, sum1, 1);
        sum1 += __shfl_xor_sync(0xffffffffu, sum1, 2);
        if ((lane & 3) == 0) {
            sPsum[row0 * 2 + warpS] = sum0;
            sPsum[row1 * 2 + warpS] = sum1;
        }
        // write p hi/lo into A-buf1 (chunk3 dec, dead now)
        #pragma unroll
        for (int nt = 0; nt < 4; nt++) {
            int colb = warpS * 32 + nt * 8 + cc;
            unsigned short h0, l0, h1, l1, h2, l2, h3, l3;
            bsplit(sacc[nt][0], h0, l0); bsplit(sacc[nt][1], h1, l1);
            bsplit(sacc[nt][2], h2, l2); bsplit(sacc[nt][3], h3, l3);
            *(uint32_t*)&pH[row0 * 72 + colb] = pack2(h0, h1);
            *(uint32_t*)&pL[row0 * 72 + colb] = pack2(l0, l1);
            *(uint32_t*)&pH[row1 * 72 + colb] = pack2(h2, h3);
            *(uint32_t*)&pL[row1 * 72 + colb] = pack2(l2, l3);
        }
        __syncthreads();

        lreg0 = lreg0 * scl0 + sPsum[row0 * 2] + sPsum[row0 * 2 + 1];
        lreg1 = lreg1 * scl1 + sPsum[row1 * 2] + sPsum[row1 * 2 + 1];
        #pragma unroll
        for (int i = 0; i < 2; i++)
            #pragma unroll
            for (int j = 0; j < 8; j++) {
                ctx[i][j][0] *= scl0; ctx[i][j][1] *= scl0;
                ctx[i][j][2] *= scl1; ctx[i][j][3] *= scl1;
            }

        // ---------------- context GEMM: ctx += p @ enc ---------------------
        #pragma unroll
        for (int ec = 0; ec < 2; ec++) {
            #pragma unroll
            for (int ks = 0; ks < 4; ks++) {
                int kb = ks * 16;
                int ar = warpT * 16 + r;
                int ac = kb + cc;
                uint32_t aH[4], aL[4];
                aH[0] = *(uint32_t*)&pH[ar * 72 + ac];
                aH[1] = *(uint32_t*)&pH[(ar + 8) * 72 + ac];
                aH[2] = *(uint32_t*)&pH[ar * 72 + ac + 8];
                aH[3] = *(uint32_t*)&pH[(ar + 8) * 72 + ac + 8];
                aL[0] = *(uint32_t*)&pL[ar * 72 + ac];
                aL[1] = *(uint32_t*)&pL[(ar + 8) * 72 + ac];
                aL[2] = *(uint32_t*)&pL[ar * 72 + ac + 8];
                aL[3] = *(uint32_t*)&pL[(ar + 8) * 72 + ac + 8];
                uint32_t lrow = (uint32_t)(ks * 16 + (lane & 15));
                uint32_t lcol0 = (uint32_t)(warpS * 64 + ((lane >> 4) << 3));
                #pragma unroll
                for (int pair = 0; pair < 4; pair++) {
                    uint32_t off = (lrow * 136 + lcol0 + pair * 16) * 2;
                    uint32_t bh0, bh1, bh2, bh3, bl0, bl1, bl2, bl3;
                    ldsm_x4_t(bh0, bh1, bh2, bh3, encHb + off);
                    ldsm_x4_t(bl0, bl1, bl2, bl3, encLb + off);
                    uint32_t bH0[2] = {bh0, bh1}, bH1[2] = {bh2, bh3};
                    uint32_t bL0[2] = {bl0, bl1}, bL1[2] = {bl2, bl3};
                    int nt = pair * 2;
                    mma16816(ctx[ec][nt], aH, bH0);
                    mma16816(ctx[ec][nt], aH, bL0);
                    mma16816(ctx[ec][nt], aL, bH0);
                    mma16816(ctx[ec][nt + 1], aH, bH1);
                    mma16816(ctx[ec][nt + 1], aH, bL1);
                    mma16816(ctx[ec][nt + 1], aL, bH1);
                }
            }
            __syncthreads();   // all warps done reading enc buffer
            if (ec == 0) {
                stage_enc_chunk(base, encBase, s0, 1, tid);
                CP_COMMIT();
                CP_WAIT(0);
                __syncthreads();
            } else if (have_next) {
                stage_enc_chunk(base, encBase, s0 + 64, 0, tid);
                CP_COMMIT();
            }
        }
    }

    // ---------------- write partial (m, l, unnormalized ctx) ----------------
    size_t pmBase = (((size_t)slice * Bb + b) * Tt) + t0;
    if (warpS == 0 && (lane & 3) == 0) {
        g_pm[pmBase + row0] = mreg0;
        g_pm[pmBase + row1] = mreg1;
        g_pl[pmBase + row0] = lreg0;
        g_pl[pmBase + row1] = lreg1;
    }
    int t = t0 + row0;
    size_t obase = (((size_t)slice * Bb + b) * Tt + t) * 256;
    #pragma unroll
    for (int ec = 0; ec < 2; ec++) {
        #pragma unroll
        for (int nt = 0; nt < 8; nt++) {
            int e = ec * 128 + warpS * 64 + nt * 8 + cc;
            *(float2*)&g_pctx[obase + e] =
                make_float2(ctx[ec][nt][0], ctx[ec][nt][1]);
            *(float2*)&g_pctx[obase + 8 * 256 + e] =
                make_float2(ctx[ec][nt][2], ctx[ec][nt][3]);
        }
    }
}

// ---------------------------------------------------------------------------
// Combine: merge slice partials -> normalized ctx, split to bf16 hi/lo.
// ---------------------------------------------------------------------------
__global__ __launch_bounds__(256)
void combine_kernel()
{
    __shared__ float w[64][4];
    int tid = threadIdx.x;
    int b = blockIdx.y;
    int t0 = blockIdx.x * 64;
    int len = g_lengths[b];
    int nsl = min(NSLICE, (len + SLICE_S - 1) / SLICE_S);

    if (tid < 64) {
        int t = t0 + tid;
        float mv[4], lv[4];
        float M = -1e30f;
        for (int s = 0; s < nsl; s++) {
            size_t off = (((size_t)s * Bb + b) * Tt) + t;
            mv[s] = g_pm[off];
            lv[s] = g_pl[off];
            M = fmaxf(M, mv[s]);
        }
        float L = 0.f;
        float ws[4];
        for (int s = 0; s < nsl; s++) {
            float e = __expf(mv[s] - M);
            ws[s] = e;
            L += e * lv[s];
        }
        float inv = 1.0f / L;
        for (int s = 0; s < 4; s++)
            w[tid][s] = (s < nsl) ? ws[s] * inv : 0.f;
    }
    __syncthreads();

    int r = tid >> 2, c0 = (tid & 3) * 64;
    int t = t0 + r;
    float wr[4] = {w[r][0], w[r][1], w[r][2], w[r][3]};
    size_t eBase = (((size_t)b) * Tt + t) * 256 + c0;
    #pragma unroll 4
    for (int e = 0; e < 64; e += 4) {
        float4 acc = make_float4(0.f, 0.f, 0.f, 0.f);
        for (int s = 0; s < nsl; s++) {
            size_t off = (((size_t)s * Bb + b) * Tt + t) * 256 + c0 + e;
            float4 v = *(const float4*)&g_pctx[off];
            acc.x += wr[s] * v.x; acc.y += wr[s] * v.y;
            acc.z += wr[s] * v.z; acc.w += wr[s] * v.w;
        }
        unsigned short h0, l0, h1, l1, h2, l2, h3, l3;
        bsplit(acc.x, h0, l0); bsplit(acc.y, h1, l1);
        bsplit(acc.z, h2, l2); bsplit(acc.w, h3, l3);
        *(uint32_t*)&g_ctxH[eBase + e] = pack2(h0, h1);
        *(uint32_t*)&g_ctxH[eBase + e + 2] = pack2(h2, h3);
        *(uint32_t*)&g_ctxL[eBase + e] = pack2(l0, l1);
        *(uint32_t*)&g_ctxL[eBase + e + 2] = pack2(l2, l3);
    }
}

// ---------------------------------------------------------------------------
extern "C" void kernel_launch(void* const* d_in, const int* in_sizes, int n_in,
                              void* d_out, int out_size)
{
    (void)in_sizes; (void)n_in; (void)out_size;
    const float* enc = (const float*)d_in[0];
    const float* dec = (const float*)d_in[1];
    const unsigned char* mask = (const unsigned char*)d_in[2];
    const float* W_enc = (const float*)d_in[3];
    const float* W_fin = (const float*)d_in[4];
    float* out = (float*)d_out;

    void *pEncH, *pEncL, *pDecH, *pDecL, *pProjH, *pProjL;
    void *pCtxH, *pCtxL, *pWeH, *pWeL, *pWfH, *pWfL;
    cudaGetSymbolAddress(&pEncH, g_encH);
    cudaGetSymbolAddress(&pEncL, g_encL);
    cudaGetSymbolAddress(&pDecH, g_decH);
    cudaGetSymbolAddress(&pDecL, g_decL);
    cudaGetSymbolAddress(&pProjH, g_projH);
    cudaGetSymbolAddress(&pProjL, g_projL);
    cudaGetSymbolAddress(&pCtxH, g_ctxH);
    cudaGetSymbolAddress(&pCtxL, g_ctxL);
    cudaGetSymbolAddress(&pWeH, g_WencTH);
    cudaGetSymbolAddress(&pWeL, g_WencTL);
    cudaGetSymbolAddress(&pWfH, g_WfinTH);
    cudaGetSymbolAddress(&pWfL, g_WfinTL);

    cudaFuncSetAttribute((const void*)mma_gemm_kernel<256, false>,
                         cudaFuncAttributeMaxDynamicSharedMemorySize, GSM_TOTAL);
    cudaFuncSetAttribute((const void*)mma_gemm_kernel<512, true>,
                         cudaFuncAttributeMaxDynamicSharedMemorySize, GSM_TOTAL);
    cudaFuncSetAttribute((const void*)attn_kernel,
                         cudaFuncAttributeMaxDynamicSharedMemorySize, A_TOTAL);

    detect_lengths_kernel<<<1, 256>>>(mask);
    prep_convert_kernel<<<1024, 256>>>(enc, dec, W_enc, W_fin);

    dim3 g1(2, 256);
    mma_gemm_kernel<256, false><<<g1, 256, GSM_TOTAL>>>(
        (const __nv_bfloat16*)pEncH, (const __nv_bfloat16*)pEncL,
        nullptr, nullptr,
        (const __nv_bfloat16*)pWeH, (const __nv_bfloat16*)pWeL,
        nullptr, (__nv_bfloat16*)pProjH, (__nv_bfloat16*)pProjL);

    dim3 g2(Tt / 64, Bb, NSLICE);
    attn_kernel<<<g2, 256, A_TOTAL>>>();

    dim3 gc(Tt / 64, Bb);
    combine_kernel<<<gc, 256>>>();

    dim3 g3(2, 128);
    mma_gemm_kernel<512, true><<<g3, 256, GSM_TOTAL>>>(
        (const __nv_bfloat16*)pCtxH, (const __nv_bfloat16*)pCtxL,
        (const __nv_bfloat16*)pDecH, (const __nv_bfloat16*)pDecL,
        (const __nv_bfloat16*)pWfH, (const __nv_bfloat16*)pWfL,
        out, nullptr, nullptr);
}

// round 7
// speedup vs baseline: 1.2698x; 1.1245x over previous
#include <cuda_runtime.h>
#include <cuda_bf16.h>
#include <math.h>
#include <stdint.h>

#define Bb 16
#define Ss 2048
#define Tt 1024
#define Ee 256
#define Dd 256
#define NSLICE 4
#define SLICE_S 512

// ---------------------------------------------------------------------------
// Scratch (allocation-free device globals), bf16 hi/lo split representations.
// decproj = dec @ W_enc^T replaces enc-side projection (half the GEMM).
// ---------------------------------------------------------------------------
__device__ __nv_bfloat16 g_encH[Bb * Ss * Ee];
__device__ __nv_bfloat16 g_encL[Bb * Ss * Ee];
__device__ __nv_bfloat16 g_decH[Bb * Tt * Dd];
__device__ __nv_bfloat16 g_decL[Bb * Tt * Dd];
__device__ __nv_bfloat16 g_dpH[Bb * Tt * Ee];     // decproj hi
__device__ __nv_bfloat16 g_dpL[Bb * Tt * Ee];     // decproj lo
__device__ __nv_bfloat16 g_ctxH[Bb * Tt * Ee];
__device__ __nv_bfloat16 g_ctxL[Bb * Tt * Ee];
__device__ __nv_bfloat16 g_WencH[Ee * Dd];        // W_enc native [e][d]
__device__ __nv_bfloat16 g_WencL[Ee * Dd];
__device__ __nv_bfloat16 g_WfinTH[Dd * (Ee + Dd)];
__device__ __nv_bfloat16 g_WfinTL[Dd * (Ee + Dd)];
__device__ int g_lengths[Bb];
__device__ float g_pctx[NSLICE * Bb * Tt * Ee];
__device__ float g_pm[NSLICE * Bb * Tt];
__device__ float g_pl[NSLICE * Bb * Tt];

// ---------------------------------------------------------------------------
// Helpers
// ---------------------------------------------------------------------------
__device__ __forceinline__ uint32_t smem_u32(const void* p) {
    uint32_t a;
    asm("{ .reg .u64 t; cvta.to.shared.u64 t, %1; cvt.u32.u64 %0, t; }"
        : "=r"(a) : "l"(p));
    return a;
}

__device__ __forceinline__ void mma16816(float* d, const uint32_t* a,
                                         const uint32_t* b) {
    asm volatile(
        "mma.sync.aligned.m16n8k16.row.col.f32.bf16.bf16.f32 "
        "{%0,%1,%2,%3}, {%4,%5,%6,%7}, {%8,%9}, {%0,%1,%2,%3};"
        : "+f"(d[0]), "+f"(d[1]), "+f"(d[2]), "+f"(d[3])
        : "r"(a[0]), "r"(a[1]), "r"(a[2]), "r"(a[3]), "r"(b[0]), "r"(b[1]));
}

__device__ __forceinline__ void ldsm_x4_t(uint32_t& r0, uint32_t& r1,
                                          uint32_t& r2, uint32_t& r3,
                                          uint32_t addr) {
    asm volatile("ldmatrix.sync.aligned.m8n8.x4.trans.shared.b16 "
                 "{%0,%1,%2,%3}, [%4];"
                 : "=r"(r0), "=r"(r1), "=r"(r2), "=r"(r3) : "r"(addr));
}

__device__ __forceinline__ void cp16(uint32_t dst, const void* src) {
    asm volatile("cp.async.cg.shared.global [%0], [%1], 16;"
                 :: "r"(dst), "l"(src));
}
#define CP_COMMIT() asm volatile("cp.async.commit_group;")
#define CP_WAIT(N)  asm volatile("cp.async.wait_group %0;" :: "n"(N))

__device__ __forceinline__ void bsplit(float x, unsigned short& h,
                                       unsigned short& l) {
    __nv_bfloat16 hb = __float2bfloat16(x);
    __nv_bfloat16 lb = __float2bfloat16(x - __bfloat162float(hb));
    h = *(unsigned short*)&hb;
    l = *(unsigned short*)&lb;
}

__device__ __forceinline__ uint32_t pack2(unsigned short a, unsigned short b) {
    return (uint32_t)a | ((uint32_t)b << 16);
}

// ---------------------------------------------------------------------------
// Mask prologue (handles uint8 or int32 bool encodings)
// ---------------------------------------------------------------------------
__global__ void detect_lengths_kernel(const unsigned char* __restrict__ mask)
{
    __shared__ int s_flag;
    __shared__ int s_cnt[Bb];
    int tid = threadIdx.x;
    if (tid == 0) s_flag = 0;
    if (tid < Bb) s_cnt[tid] = 0;
    __syncthreads();

    int local = 0;
    for (int i = tid; i < Bb * Ss; i += 256)
        if ((i & 3) != 0 && mask[i] != 0) local = 1;
    if (local) atomicOr(&s_flag, 1);
    __syncthreads();

    bool isU8 = (s_flag != 0);
    int row = tid >> 4, part = tid & 15;
    int cnt = 0;
    if (isU8) {
        const unsigned char* p = mask + row * Ss + part * 128;
        #pragma unroll 4
        for (int e = 0; e < 128; e++) cnt += (p[e] != 0);
    } else {
        const int* p = ((const int*)mask) + row * Ss + part * 128;
        #pragma unroll 4
        for (int e = 0; e < 128; e++) cnt += (p[e] != 0);
    }
    atomicAdd(&s_cnt[row], cnt);
    __syncthreads();
    if (tid < Bb) g_lengths[tid] = s_cnt[tid];
}

// ---------------------------------------------------------------------------
// Prep: fp32 -> bf16 hi/lo for enc, dec; W_enc split (no transpose);
// W_fin transposed+split.
// ---------------------------------------------------------------------------
__global__ void prep_convert_kernel(const float* __restrict__ enc,
                                    const float* __restrict__ dec,
                                    const float* __restrict__ Wenc,
                                    const float* __restrict__ Wfin)
{
    int tid = blockIdx.x * blockDim.x + threadIdx.x;
    int stride = gridDim.x * blockDim.x;

    const int NE4 = (Bb * Ss * Ee) / 4;
    for (int i = tid; i < NE4; i += stride) {
        float4 v = ((const float4*)enc)[i];
        ushort4 hv, lv;
        bsplit(v.x, hv.x, lv.x); bsplit(v.y, hv.y, lv.y);
        bsplit(v.z, hv.z, lv.z); bsplit(v.w, hv.w, lv.w);
        ((ushort4*)g_encH)[i] = hv;
        ((ushort4*)g_encL)[i] = lv;
    }
    const int ND4 = (Bb * Tt * Dd) / 4;
    for (int i = tid; i < ND4; i += stride) {
        float4 v = ((const float4*)dec)[i];
        ushort4 hv, lv;
        bsplit(v.x, hv.x, lv.x); bsplit(v.y, hv.y, lv.y);
        bsplit(v.z, hv.z, lv.z); bsplit(v.w, hv.w, lv.w);
        ((ushort4*)g_decH)[i] = hv;
        ((ushort4*)g_decL)[i] = lv;
    }
    for (int i = tid; i < 256 * 256; i += stride) {
        unsigned short h, l;
        bsplit(Wenc[i], h, l);               // native [e][d] layout
        *(unsigned short*)&g_WencH[i] = h;
        *(unsigned short*)&g_WencL[i] = l;
    }
    for (int i = tid; i < 256 * 512; i += stride) {
        int d = i >> 9, f = i & 511;
        unsigned short h, l;
        bsplit(Wfin[f * 256 + d], h, l);
        *(unsigned short*)&g_WfinTH[i] = h;
        *(unsigned short*)&g_WfinTL[i] = l;
    }
}

// ---------------------------------------------------------------------------
// Split-bf16 tensor-core GEMM (round-4 proven version)
// ---------------------------------------------------------------------------
#define GSM_A_H 0
#define GSM_A_L 18432
#define GSM_B_H 36864
#define GSM_B_L 55296
#define GSM_TOTAL 73728

template<int KTOT, bool TANH>
__global__ __launch_bounds__(256, 2)
void mma_gemm_kernel(const __nv_bfloat16* __restrict__ A1H,
                     const __nv_bfloat16* __restrict__ A1L,
                     const __nv_bfloat16* __restrict__ A2H,
                     const __nv_bfloat16* __restrict__ A2L,
                     const __nv_bfloat16* __restrict__ BTH,
                     const __nv_bfloat16* __restrict__ BTL,
                     float* __restrict__ Cf,
                     __nv_bfloat16* __restrict__ CH,
                     __nv_bfloat16* __restrict__ CL)
{
    extern __shared__ char dyn[];
    __nv_bfloat16* sAH = (__nv_bfloat16*)(dyn + GSM_A_H);
    __nv_bfloat16* sAL = (__nv_bfloat16*)(dyn + GSM_A_L);
    __nv_bfloat16* sBH = (__nv_bfloat16*)(dyn + GSM_B_H);
    __nv_bfloat16* sBL = (__nv_bfloat16*)(dyn + GSM_B_L);

    int tid = threadIdx.x, lane = tid & 31, wid = tid >> 5;
    int warpM = wid & 3, warpN = wid >> 2;
    int m0 = blockIdx.y * 128, n0 = blockIdx.x * 128;
    int r = lane >> 2, cc = (lane & 3) * 2;

    float acc[2][8][4];
    #pragma unroll
    for (int i = 0; i < 2; i++)
        #pragma unroll
        for (int j = 0; j < 8; j++)
            #pragma unroll
            for (int q = 0; q < 4; q++) acc[i][j][q] = 0.f;

    for (int kc = 0; kc < KTOT; kc += 64) {
        const __nv_bfloat16* AH = A1H;
        const __nv_bfloat16* AL = A1L;
        int kcol = kc;
        if (KTOT > 256 && kc >= 256) { AH = A2H; AL = A2L; kcol = kc - 256; }

        #pragma unroll
        for (int u = 0; u < 4; u++) {
            int f = tid + u * 256;
            int rr = f >> 3, c8 = f & 7;
            *(uint4*)&sAH[rr * 72 + c8 * 8] =
                *(const uint4*)&AH[(size_t)(m0 + rr) * 256 + kcol + c8 * 8];
            *(uint4*)&sAL[rr * 72 + c8 * 8] =
                *(const uint4*)&AL[(size_t)(m0 + rr) * 256 + kcol + c8 * 8];
            *(uint4*)&sBH[rr * 72 + c8 * 8] =
                *(const uint4*)&BTH[(size_t)(n0 + rr) * KTOT + kc + c8 * 8];
            *(uint4*)&sBL[rr * 72 + c8 * 8] =
                *(const uint4*)&BTL[(size_t)(n0 + rr) * KTOT + kc + c8 * 8];
        }
        __syncthreads();

        #pragma unroll
        for (int ks = 0; ks < 4; ks++) {
            int k0 = ks * 16;
            uint32_t aH[2][4], aL[2][4];
            #pragma unroll
            for (int mt = 0; mt < 2; mt++) {
                int ar = warpM * 32 + mt * 16 + r;
                int ac = k0 + cc;
                aH[mt][0] = *(uint32_t*)&sAH[ar * 72 + ac];
                aH[mt][1] = *(uint32_t*)&sAH[(ar + 8) * 72 + ac];
                aH[mt][2] = *(uint32_t*)&sAH[ar * 72 + ac + 8];
                aH[mt][3] = *(uint32_t*)&sAH[(ar + 8) * 72 + ac + 8];
                aL[mt][0] = *(uint32_t*)&sAL[ar * 72 + ac];
                aL[mt][1] = *(uint32_t*)&sAL[(ar + 8) * 72 + ac];
                aL[mt][2] = *(uint32_t*)&sAL[ar * 72 + ac + 8];
                aL[mt][3] = *(uint32_t*)&sAL[(ar + 8) * 72 + ac + 8];
            }
            #pragma unroll
            for (int nt = 0; nt < 8; nt++) {
                int bn = warpN * 64 + nt * 8 + r;
                int bc = k0 + cc;
                uint32_t bH[2], bL[2];
                bH[0] = *(uint32_t*)&sBH[bn * 72 + bc];
                bH[1] = *(uint32_t*)&sBH[bn * 72 + bc + 8];
                bL[0] = *(uint32_t*)&sBL[bn * 72 + bc];
                bL[1] = *(uint32_t*)&sBL[bn * 72 + bc + 8];
                #pragma unroll
                for (int mt = 0; mt < 2; mt++) {
                    mma16816(acc[mt][nt], aH[mt], bH);
                    mma16816(acc[mt][nt], aH[mt], bL);
                    mma16816(acc[mt][nt], aL[mt], bH);
                }
            }
        }
        __syncthreads();
    }

    #pragma unroll
    for (int mt = 0; mt < 2; mt++) {
        #pragma unroll
        for (int nt = 0; nt < 8; nt++) {
            int m = m0 + warpM * 32 + mt * 16 + r;
            int n = n0 + warpN * 64 + nt * 8 + cc;
            float c0 = acc[mt][nt][0], c1 = acc[mt][nt][1];
            float c2 = acc[mt][nt][2], c3 = acc[mt][nt][3];
            if (TANH) {
                float2 v0 = make_float2(tanhf(c0), tanhf(c1));
                float2 v1 = make_float2(tanhf(c2), tanhf(c3));
                *(float2*)&Cf[(size_t)m * 256 + n] = v0;
                *(float2*)&Cf[(size_t)(m + 8) * 256 + n] = v1;
            } else {
                unsigned short h0, l0, h1, l1, h2, l2, h3, l3;
                bsplit(c0, h0, l0); bsplit(c1, h1, l1);
                bsplit(c2, h2, l2); bsplit(c3, h3, l3);
                *(uint32_t*)&CH[(size_t)m * 256 + n] = pack2(h0, h1);
                *(uint32_t*)&CL[(size_t)m * 256 + n] = pack2(l0, l1);
                *(uint32_t*)&CH[(size_t)(m + 8) * 256 + n] = pack2(h2, h3);
                *(uint32_t*)&CL[(size_t)(m + 8) * 256 + n] = pack2(l2, l3);
            }
        }
    }
}

// ---------------------------------------------------------------------------
// Fused flash attention, split-KV. Score B-operand IS enc (decproj trick),
// so the 4 enc k-chunks staged during the score pipeline are reused by the
// context GEMM via ldmatrix.trans — no second staging stream.
// smem layout (bytes):
//   A bufs (decproj 64x72 hi+lo) x2: 0/9216/18432/27648  (buf1 reused as p)
//   enc chunks [ch] hi/lo: 36864 + ch*18432 (+9216 for lo), ch = 0..3
//   pmax/psum: 110592 / 111104
// ---------------------------------------------------------------------------
#define O_AH0 0
#define O_AL0 9216
#define O_AH1 18432
#define O_AL1 27648
#define O_E   36864
#define O_PMAX 110592
#define O_PSUM 111104
#define A_TOTAL 111616

__device__ __forceinline__ void stage_chunk(uint32_t base, int abuf, int ch,
                                            size_t dpBase, size_t encBase,
                                            int s0, int tid)
{
    uint32_t ah = base + (abuf ? O_AH1 : O_AH0);
    uint32_t al = ah + 9216;
    uint32_t eh = base + O_E + ch * 18432;
    uint32_t el = eh + 9216;
    int kc = ch * 64;
    #pragma unroll
    for (int u = 0; u < 2; u++) {
        int f = tid + u * 256;
        int rr = f >> 3, c = f & 7;
        uint32_t doff = rr * 144 + c * 16;
        size_t ga = dpBase + (size_t)rr * 256 + kc + c * 8;
        size_t ge = encBase + (size_t)(s0 + rr) * 256 + kc + c * 8;
        cp16(ah + doff, g_dpH + ga);
        cp16(al + doff, g_dpL + ga);
        cp16(eh + doff, g_encH + ge);
        cp16(el + doff, g_encL + ge);
    }
}

__global__ __launch_bounds__(256, 2)
void attn_kernel()
{
    extern __shared__ char dyn[];
    uint32_t base = smem_u32(dyn);
    float* sPmax = (float*)(dyn + O_PMAX);
    float* sPsum = (float*)(dyn + O_PSUM);
    __nv_bfloat16* pH = (__nv_bfloat16*)(dyn + O_AH1);
    __nv_bfloat16* pL = (__nv_bfloat16*)(dyn + O_AL1);

    int tid = threadIdx.x, lane = tid & 31, wid = tid >> 5;
    int warpT = wid & 3;
    int warpS = wid >> 2;
    int r = lane >> 2, cc = (lane & 3) * 2;
    int b = blockIdx.y;
    int t0 = blockIdx.x * 64;
    int slice = blockIdx.z;
    int len = g_lengths[b];

    int sbeg = slice * SLICE_S;
    if (sbeg >= len) return;
    int send = min(sbeg + SLICE_S, len);

    size_t dpBase = ((size_t)b * Tt + t0) * 256;
    size_t encBase = (size_t)b * Ss * 256;

    int row0 = warpT * 16 + r;
    int row1 = row0 + 8;
    float mreg0 = -1e30f, mreg1 = -1e30f;
    float lreg0 = 0.f, lreg1 = 0.f;

    float ctx[4][4][4];   // [e-chunk][nt][quad]
    #pragma unroll
    for (int i = 0; i < 4; i++)
        #pragma unroll
        for (int j = 0; j < 4; j++)
            #pragma unroll
            for (int q = 0; q < 4; q++) ctx[i][j][q] = 0.f;

    // prologue: chunk0 of first tile
    stage_chunk(base, 0, 0, dpBase, encBase, sbeg, tid);
    CP_COMMIT();

    for (int s0 = sbeg; s0 < send; s0 += 64) {
        bool have_next = (s0 + 64 < send);

        // ---------------- score GEMM: 64t x 64s, K(e)=256 in 4 chunks ------
        float sacc[4][4];
        #pragma unroll
        for (int j = 0; j < 4; j++)
            #pragma unroll
            for (int q = 0; q < 4; q++) sacc[j][q] = 0.f;

        #pragma unroll
        for (int kch = 0; kch < 4; kch++) {
            if (kch < 3) {
                stage_chunk(base, (kch + 1) & 1, kch + 1, dpBase, encBase,
                            s0, tid);
                CP_COMMIT();
                CP_WAIT(1);
            } else {
                CP_WAIT(0);
            }
            __syncthreads();

            const __nv_bfloat16* sAH =
                (const __nv_bfloat16*)(dyn + ((kch & 1) ? O_AH1 : O_AH0));
            const __nv_bfloat16* sAL = sAH + 4608;  // +9216 bytes
            const __nv_bfloat16* sBH =
                (const __nv_bfloat16*)(dyn + O_E + kch * 18432);
            const __nv_bfloat16* sBL = sBH + 4608;

            #pragma unroll
            for (int ks = 0; ks < 4; ks++) {
                int ac = ks * 16 + cc;
                int ar = warpT * 16 + r;
                uint32_t aH[4], aL[4];
                aH[0] = *(uint32_t*)&sAH[ar * 72 + ac];
                aH[1] = *(uint32_t*)&sAH[(ar + 8) * 72 + ac];
                aH[2] = *(uint32_t*)&sAH[ar * 72 + ac + 8];
                aH[3] = *(uint32_t*)&sAH[(ar + 8) * 72 + ac + 8];
                aL[0] = *(uint32_t*)&sAL[ar * 72 + ac];
                aL[1] = *(uint32_t*)&sAL[(ar + 8) * 72 + ac];
                aL[2] = *(uint32_t*)&sAL[ar * 72 + ac + 8];
                aL[3] = *(uint32_t*)&sAL[(ar + 8) * 72 + ac + 8];
                #pragma unroll
                for (int nt = 0; nt < 4; nt++) {
                    int bn = warpS * 32 + nt * 8 + r;
                    uint32_t bH[2], bL[2];
                    bH[0] = *(uint32_t*)&sBH[bn * 72 + ac];
                    bH[1] = *(uint32_t*)&sBH[bn * 72 + ac + 8];
                    bL[0] = *(uint32_t*)&sBL[bn * 72 + ac];
                    bL[1] = *(uint32_t*)&sBL[bn * 72 + ac + 8];
                    mma16816(sacc[nt], aH, bH);
                    mma16816(sacc[nt], aH, bL);
                    mma16816(sacc[nt], aL, bH);
                }
            }
            __syncthreads();
        }

        // ---------------- register softmax ---------------------------------
        float rm0 = -1e30f, rm1 = -1e30f;
        #pragma unroll
        for (int nt = 0; nt < 4; nt++) {
            int cg = s0 + warpS * 32 + nt * 8 + cc;
            if (cg >= len)     { sacc[nt][0] = -1e30f; sacc[nt][2] = -1e30f; }
            if (cg + 1 >= len) { sacc[nt][1] = -1e30f; sacc[nt][3] = -1e30f; }
            rm0 = fmaxf(rm0, fmaxf(sacc[nt][0], sacc[nt][1]));
            rm1 = fmaxf(rm1, fmaxf(sacc[nt][2], sacc[nt][3]));
        }
        rm0 = fmaxf(rm0, __shfl_xor_sync(0xffffffffu, rm0, 1));
        rm0 = fmaxf(rm0, __shfl_xor_sync(0xffffffffu, rm0, 2));
        rm1 = fmaxf(rm1, __shfl_xor_sync(0xffffffffu, rm1, 1));
        rm1 = fmaxf(rm1, __shfl_xor_sync(0xffffffffu, rm1, 2));
        if ((lane & 3) == 0) {
            sPmax[row0 * 2 + warpS] = rm0;
            sPmax[row1 * 2 + warpS] = rm1;
        }
        __syncthreads();

        float mN0 = fmaxf(mreg0, fmaxf(sPmax[row0 * 2], sPmax[row0 * 2 + 1]));
        float mN1 = fmaxf(mreg1, fmaxf(sPmax[row1 * 2], sPmax[row1 * 2 + 1]));
        float scl0 = __expf(mreg0 - mN0);
        float scl1 = __expf(mreg1 - mN1);
        mreg0 = mN0; mreg1 = mN1;

        float sum0 = 0.f, sum1 = 0.f;
        #pragma unroll
        for (int nt = 0; nt < 4; nt++) {
            sacc[nt][0] = __expf(sacc[nt][0] - mN0);
            sacc[nt][1] = __expf(sacc[nt][1] - mN0);
            sacc[nt][2] = __expf(sacc[nt][2] - mN1);
            sacc[nt][3] = __expf(sacc[nt][3] - mN1);
            sum0 += sacc[nt][0] + sacc[nt][1];
            sum1 += sacc[nt][2] + sacc[nt][3];
        }
        sum0 += __shfl_xor_sync(0xffffffffu, sum0, 1);
        sum0 += __shfl_xor_sync(0xffffffffu, sum0, 2);
        sum1 += __shfl_xor_sync(0xffffffffu, sum1, 1);
        sum1 += __shfl_xor_sync(0xffffffffu, sum1, 2);
        if ((lane & 3) == 0) {
            sPsum[row0 * 2 + warpS] = sum0;
            sPsum[row1 * 2 + warpS] = sum1;
        }
        // write p hi/lo into A-buf1 (chunk3's A, dead after score loop)
        #pragma unroll
        for (int nt = 0; nt < 4; nt++) {
            int colb = warpS * 32 + nt * 8 + cc;
            unsigned short h0, l0, h1, l1, h2, l2, h3, l3;
            bsplit(sacc[nt][0], h0, l0); bsplit(sacc[nt][1], h1, l1);
            bsplit(sacc[nt][2], h2, l2); bsplit(sacc[nt][3], h3, l3);
            *(uint32_t*)&pH[row0 * 72 + colb] = pack2(h0, h1);
            *(uint32_t*)&pL[row0 * 72 + colb] = pack2(l0, l1);
            *(uint32_t*)&pH[row1 * 72 + colb] = pack2(h2, h3);
            *(uint32_t*)&pL[row1 * 72 + colb] = pack2(l2, l3);
        }
        __syncthreads();

        lreg0 = lreg0 * scl0 + sPsum[row0 * 2] + sPsum[row0 * 2 + 1];
        lreg1 = lreg1 * scl1 + sPsum[row1 * 2] + sPsum[row1 * 2 + 1];
        #pragma unroll
        for (int i = 0; i < 4; i++)
            #pragma unroll
            for (int j = 0; j < 4; j++) {
                ctx[i][j][0] *= scl0; ctx[i][j][1] *= scl0;
                ctx[i][j][2] *= scl1; ctx[i][j][3] *= scl1;
            }

        // ---------------- context GEMM: ctx += p @ enc (reuse E chunks) ----
        #pragma unroll
        for (int ch = 0; ch < 4; ch++) {
            uint32_t ehb = base + O_E + ch * 18432;
            uint32_t elb = ehb + 9216;
            #pragma unroll
            for (int ks = 0; ks < 4; ks++) {
                int ac = ks * 16 + cc;
                int ar = warpT * 16 + r;
                uint32_t aH[4], aL[4];
                aH[0] = *(uint32_t*)&pH[ar * 72 + ac];
                aH[1] = *(uint32_t*)&pH[(ar + 8) * 72 + ac];
                aH[2] = *(uint32_t*)&pH[ar * 72 + ac + 8];
                aH[3] = *(uint32_t*)&pH[(ar + 8) * 72 + ac + 8];
                aL[0] = *(uint32_t*)&pL[ar * 72 + ac];
                aL[1] = *(uint32_t*)&pL[(ar + 8) * 72 + ac];
                aL[2] = *(uint32_t*)&pL[ar * 72 + ac + 8];
                aL[3] = *(uint32_t*)&pL[(ar + 8) * 72 + ac + 8];
                uint32_t lrow = (uint32_t)(ks * 16 + (lane & 15));
                uint32_t lcol0 = (uint32_t)(warpS * 32 + ((lane >> 4) << 3));
                #pragma unroll
                for (int pair = 0; pair < 2; pair++) {
                    uint32_t off = (lrow * 72 + lcol0 + pair * 16) * 2;
                    uint32_t bh0, bh1, bh2, bh3, bl0, bl1, bl2, bl3;
                    ldsm_x4_t(bh0, bh1, bh2, bh3, ehb + off);
                    ldsm_x4_t(bl0, bl1, bl2, bl3, elb + off);
                    uint32_t bH0[2] = {bh0, bh1}, bH1[2] = {bh2, bh3};
                    uint32_t bL0[2] = {bl0, bl1}, bL1[2] = {bl2, bl3};
                    int nt = pair * 2;
                    mma16816(ctx[ch][nt], aH, bH0);
                    mma16816(ctx[ch][nt], aH, bL0);
                    mma16816(ctx[ch][nt], aL, bH0);
                    mma16816(ctx[ch][nt + 1], aH, bH1);
                    mma16816(ctx[ch][nt + 1], aH, bL1);
                    mma16816(ctx[ch][nt + 1], aL, bH1);
                }
            }
            if (ch == 0) {
                __syncthreads();               // all warps done with E0
                if (have_next) {
                    stage_chunk(base, 0, 0, dpBase, encBase, s0 + 64, tid);
                    CP_COMMIT();
                }
            }
        }
        __syncthreads();   // p + E1..E3 free for next tile's staging
    }

    // ---------------- write partial (m, l, unnormalized ctx) ----------------
    size_t pmBase = (((size_t)slice * Bb + b) * Tt) + t0;
    if (warpS == 0 && (lane & 3) == 0) {
        g_pm[pmBase + row0] = mreg0;
        g_pm[pmBase + row1] = mreg1;
        g_pl[pmBase + row0] = lreg0;
        g_pl[pmBase + row1] = lreg1;
    }
    int t = t0 + row0;
    size_t obase = (((size_t)slice * Bb + b) * Tt + t) * 256;
    #pragma unroll
    for (int ch = 0; ch < 4; ch++) {
        #pragma unroll
        for (int nt = 0; nt < 4; nt++) {
            int e = ch * 64 + warpS * 32 + nt * 8 + cc;
            *(float2*)&g_pctx[obase + e] =
                make_float2(ctx[ch][nt][0], ctx[ch][nt][1]);
            *(float2*)&g_pctx[obase + 8 * 256 + e] =
                make_float2(ctx[ch][nt][2], ctx[ch][nt][3]);
        }
    }
}

// ---------------------------------------------------------------------------
// Combine: merge slice partials -> normalized ctx, split to bf16 hi/lo.
// ---------------------------------------------------------------------------
__global__ __launch_bounds__(256)
void combine_kernel()
{
    __shared__ float w[64][4];
    int tid = threadIdx.x;
    int b = blockIdx.y;
    int t0 = blockIdx.x * 64;
    int len = g_lengths[b];
    int nsl = min(NSLICE, (len + SLICE_S - 1) / SLICE_S);

    if (tid < 64) {
        int t = t0 + tid;
        float mv[4], lv[4];
        float M = -1e30f;
        for (int s = 0; s < nsl; s++) {
            size_t off = (((size_t)s * Bb + b) * Tt) + t;
            mv[s] = g_pm[off];
            lv[s] = g_pl[off];
            M = fmaxf(M, mv[s]);
        }
        float L = 0.f;
        float ws[4];
        for (int s = 0; s < nsl; s++) {
            float e = __expf(mv[s] - M);
            ws[s] = e;
            L += e * lv[s];
        }
        float inv = 1.0f / L;
        for (int s = 0; s < 4; s++)
            w[tid][s] = (s < nsl) ? ws[s] * inv : 0.f;
    }
    __syncthreads();

    int r = tid >> 2, c0 = (tid & 3) * 64;
    int t = t0 + r;
    float wr[4] = {w[r][0], w[r][1], w[r][2], w[r][3]};
    size_t eBase = (((size_t)b) * Tt + t) * 256 + c0;
    #pragma unroll 4
    for (int e = 0; e < 64; e += 4) {
        float4 acc = make_float4(0.f, 0.f, 0.f, 0.f);
        for (int s = 0; s < nsl; s++) {
            size_t off = (((size_t)s * Bb + b) * Tt + t) * 256 + c0 + e;
            float4 v = *(const float4*)&g_pctx[off];
            acc.x += wr[s] * v.x; acc.y += wr[s] * v.y;
            acc.z += wr[s] * v.z; acc.w += wr[s] * v.w;
        }
        unsigned short h0, l0, h1, l1, h2, l2, h3, l3;
        bsplit(acc.x, h0, l0); bsplit(acc.y, h1, l1);
        bsplit(acc.z, h2, l2); bsplit(acc.w, h3, l3);
        *(uint32_t*)&g_ctxH[eBase + e] = pack2(h0, h1);
        *(uint32_t*)&g_ctxH[eBase + e + 2] = pack2(h2, h3);
        *(uint32_t*)&g_ctxL[eBase + e] = pack2(l0, l1);
        *(uint32_t*)&g_ctxL[eBase + e + 2] = pack2(l2, l3);
    }
}

// ---------------------------------------------------------------------------
extern "C" void kernel_launch(void* const* d_in, const int* in_sizes, int n_in,
                              void* d_out, int out_size)
{
    (void)in_sizes; (void)n_in; (void)out_size;
    const float* enc = (const float*)d_in[0];
    const float* dec = (const float*)d_in[1];
    const unsigned char* mask = (const unsigned char*)d_in[2];
    const float* W_enc = (const float*)d_in[3];
    const float* W_fin = (const float*)d_in[4];
    float* out = (float*)d_out;

    void *pDecH, *pDecL, *pDpH, *pDpL;
    void *pCtxH, *pCtxL, *pWeH, *pWeL, *pWfH, *pWfL;
    cudaGetSymbolAddress(&pDecH, g_decH);
    cudaGetSymbolAddress(&pDecL, g_decL);
    cudaGetSymbolAddress(&pDpH, g_dpH);
    cudaGetSymbolAddress(&pDpL, g_dpL);
    cudaGetSymbolAddress(&pCtxH, g_ctxH);
    cudaGetSymbolAddress(&pCtxL, g_ctxL);
    cudaGetSymbolAddress(&pWeH, g_WencH);
    cudaGetSymbolAddress(&pWeL, g_WencL);
    cudaGetSymbolAddress(&pWfH, g_WfinTH);
    cudaGetSymbolAddress(&pWfL, g_WfinTL);

    cudaFuncSetAttribute((const void*)mma_gemm_kernel<256, false>,
                         cudaFuncAttributeMaxDynamicSharedMemorySize, GSM_TOTAL);
    cudaFuncSetAttribute((const void*)mma_gemm_kernel<512, true>,
                         cudaFuncAttributeMaxDynamicSharedMemorySize, GSM_TOTAL);
    cudaFuncSetAttribute((const void*)attn_kernel,
                         cudaFuncAttributeMaxDynamicSharedMemorySize, A_TOTAL);

    detect_lengths_kernel<<<1, 256>>>(mask);
    prep_convert_kernel<<<1024, 256>>>(enc, dec, W_enc, W_fin);

    // GEMM1': decproj = dec @ W_enc^T  (M=16384, N=256, K=256)
    dim3 g1(2, 128);
    mma_gemm_kernel<256, false><<<g1, 256, GSM_TOTAL>>>(
        (const __nv_bfloat16*)pDecH, (const __nv_bfloat16*)pDecL,
        nullptr, nullptr,
        (const __nv_bfloat16*)pWeH, (const __nv_bfloat16*)pWeL,
        nullptr, (__nv_bfloat16*)pDpH, (__nv_bfloat16*)pDpL);

    dim3 g2(Tt / 64, Bb, NSLICE);
    attn_kernel<<<g2, 256, A_TOTAL>>>();

    dim3 gc(Tt / 64, Bb);
    combine_kernel<<<gc, 256>>>();

    dim3 g3(2, 128);
    mma_gemm_kernel<512, true><<<g3, 256, GSM_TOTAL>>>(
        (const __nv_bfloat16*)pCtxH, (const __nv_bfloat16*)pCtxL,
        (const __nv_bfloat16*)pDecH, (const __nv_bfloat16*)pDecL,
        (const __nv_bfloat16*)pWfH, (const __nv_bfloat16*)pWfL,
        out, nullptr, nullptr);
}

// round 8
// speedup vs baseline: 1.3823x; 1.0886x over previous
#include <cuda_runtime.h>
#include <cuda_bf16.h>
#include <math.h>
#include <stdint.h>

#define Bb 16
#define Ss 2048
#define Tt 1024
#define Ee 256
#define Dd 256
#define NSLICE 4
#define SLICE_S 512
#define MTOT (Bb * Tt)   // 16384

// ---------------------------------------------------------------------------
// Scratch (allocation-free device globals), bf16 hi/lo split representations.
// ---------------------------------------------------------------------------
__device__ __nv_bfloat16 g_encH[Bb * Ss * Ee];
__device__ __nv_bfloat16 g_encL[Bb * Ss * Ee];
__device__ __nv_bfloat16 g_decH[Bb * Tt * Dd];
__device__ __nv_bfloat16 g_decL[Bb * Tt * Dd];
__device__ __nv_bfloat16 g_dpH[Bb * Tt * Ee];     // decproj hi
__device__ __nv_bfloat16 g_dpL[Bb * Tt * Ee];     // decproj lo
__device__ __nv_bfloat16 g_WencH[Ee * Dd];        // W_enc native [e][d]
__device__ __nv_bfloat16 g_WencL[Ee * Dd];
__device__ __nv_bfloat16 g_WfinTH[Dd * (Ee + Dd)];
__device__ __nv_bfloat16 g_WfinTL[Dd * (Ee + Dd)];
__device__ int g_lengths[Bb];
__device__ float g_pctx[NSLICE * MTOT * Ee];      // 67 MB fp32 partials
__device__ float g_pm[NSLICE * MTOT];
__device__ float g_pl[NSLICE * MTOT];
__device__ float g_wcomb[NSLICE * MTOT];          // combine weights

// ---------------------------------------------------------------------------
// Helpers
// ---------------------------------------------------------------------------
__device__ __forceinline__ uint32_t smem_u32(const void* p) {
    uint32_t a;
    asm("{ .reg .u64 t; cvta.to.shared.u64 t, %1; cvt.u32.u64 %0, t; }"
        : "=r"(a) : "l"(p));
    return a;
}

__device__ __forceinline__ void mma16816(float* d, const uint32_t* a,
                                         const uint32_t* b) {
    asm volatile(
        "mma.sync.aligned.m16n8k16.row.col.f32.bf16.bf16.f32 "
        "{%0,%1,%2,%3}, {%4,%5,%6,%7}, {%8,%9}, {%0,%1,%2,%3};"
        : "+f"(d[0]), "+f"(d[1]), "+f"(d[2]), "+f"(d[3])
        : "r"(a[0]), "r"(a[1]), "r"(a[2]), "r"(a[3]), "r"(b[0]), "r"(b[1]));
}

__device__ __forceinline__ void ldsm_x4_t(uint32_t& r0, uint32_t& r1,
                                          uint32_t& r2, uint32_t& r3,
                                          uint32_t addr) {
    asm volatile("ldmatrix.sync.aligned.m8n8.x4.trans.shared.b16 "
                 "{%0,%1,%2,%3}, [%4];"
                 : "=r"(r0), "=r"(r1), "=r"(r2), "=r"(r3) : "r"(addr));
}

__device__ __forceinline__ void cp16(uint32_t dst, const void* src) {
    asm volatile("cp.async.cg.shared.global [%0], [%1], 16;"
                 :: "r"(dst), "l"(src));
}
#define CP_COMMIT() asm volatile("cp.async.commit_group;")
#define CP_WAIT(N)  asm volatile("cp.async.wait_group %0;" :: "n"(N))

__device__ __forceinline__ void bsplit(float x, unsigned short& h,
                                       unsigned short& l) {
    __nv_bfloat16 hb = __float2bfloat16(x);
    __nv_bfloat16 lb = __float2bfloat16(x - __bfloat162float(hb));
    h = *(unsigned short*)&hb;
    l = *(unsigned short*)&lb;
}

__device__ __forceinline__ uint32_t pack2(unsigned short a, unsigned short b) {
    return (uint32_t)a | ((uint32_t)b << 16);
}

// ---------------------------------------------------------------------------
// Mask prologue (handles uint8 or int32 bool encodings)
// ---------------------------------------------------------------------------
__global__ void detect_lengths_kernel(const unsigned char* __restrict__ mask)
{
    __shared__ int s_flag;
    __shared__ int s_cnt[Bb];
    int tid = threadIdx.x;
    if (tid == 0) s_flag = 0;
    if (tid < Bb) s_cnt[tid] = 0;
    __syncthreads();

    int local = 0;
    for (int i = tid; i < Bb * Ss; i += 256)
        if ((i & 3) != 0 && mask[i] != 0) local = 1;
    if (local) atomicOr(&s_flag, 1);
    __syncthreads();

    bool isU8 = (s_flag != 0);
    int row = tid >> 4, part = tid & 15;
    int cnt = 0;
    if (isU8) {
        const unsigned char* p = mask + row * Ss + part * 128;
        #pragma unroll 4
        for (int e = 0; e < 128; e++) cnt += (p[e] != 0);
    } else {
        const int* p = ((const int*)mask) + row * Ss + part * 128;
        #pragma unroll 4
        for (int e = 0; e < 128; e++) cnt += (p[e] != 0);
    }
    atomicAdd(&s_cnt[row], cnt);
    __syncthreads();
    if (tid < Bb) g_lengths[tid] = s_cnt[tid];
}

// ---------------------------------------------------------------------------
// Prep: fp32 -> bf16 hi/lo for enc, dec; W_enc split (native layout);
// W_fin transposed+split.
// ---------------------------------------------------------------------------
__global__ void prep_convert_kernel(const float* __restrict__ enc,
                                    const float* __restrict__ dec,
                                    const float* __restrict__ Wenc,
                                    const float* __restrict__ Wfin)
{
    int tid = blockIdx.x * blockDim.x + threadIdx.x;
    int stride = gridDim.x * blockDim.x;

    const int NE4 = (Bb * Ss * Ee) / 4;
    for (int i = tid; i < NE4; i += stride) {
        float4 v = ((const float4*)enc)[i];
        ushort4 hv, lv;
        bsplit(v.x, hv.x, lv.x); bsplit(v.y, hv.y, lv.y);
        bsplit(v.z, hv.z, lv.z); bsplit(v.w, hv.w, lv.w);
        ((ushort4*)g_encH)[i] = hv;
        ((ushort4*)g_encL)[i] = lv;
    }
    const int ND4 = (Bb * Tt * Dd) / 4;
    for (int i = tid; i < ND4; i += stride) {
        float4 v = ((const float4*)dec)[i];
        ushort4 hv, lv;
        bsplit(v.x, hv.x, lv.x); bsplit(v.y, hv.y, lv.y);
        bsplit(v.z, hv.z, lv.z); bsplit(v.w, hv.w, lv.w);
        ((ushort4*)g_decH)[i] = hv;
        ((ushort4*)g_decL)[i] = lv;
    }
    for (int i = tid; i < 256 * 256; i += stride) {
        unsigned short h, l;
        bsplit(Wenc[i], h, l);
        *(unsigned short*)&g_WencH[i] = h;
        *(unsigned short*)&g_WencL[i] = l;
    }
    for (int i = tid; i < 256 * 512; i += stride) {
        int d = i >> 9, f = i & 511;
        unsigned short h, l;
        bsplit(Wfin[f * 256 + d], h, l);
        *(unsigned short*)&g_WfinTH[i] = h;
        *(unsigned short*)&g_WfinTL[i] = l;
    }
}

// ---------------------------------------------------------------------------
// Split-bf16 tensor-core GEMM for GEMM1' (decproj), KTOT=256, bf16 out.
// ---------------------------------------------------------------------------
#define GSM_A_H 0
#define GSM_A_L 18432
#define GSM_B_H 36864
#define GSM_B_L 55296
#define GSM_TOTAL 73728

__global__ __launch_bounds__(256, 2)
void mma_gemm1_kernel(const __nv_bfloat16* __restrict__ A1H,
                      const __nv_bfloat16* __restrict__ A1L,
                      const __nv_bfloat16* __restrict__ BTH,
                      const __nv_bfloat16* __restrict__ BTL,
                      __nv_bfloat16* __restrict__ CH,
                      __nv_bfloat16* __restrict__ CL)
{
    extern __shared__ char dyn[];
    __nv_bfloat16* sAH = (__nv_bfloat16*)(dyn + GSM_A_H);
    __nv_bfloat16* sAL = (__nv_bfloat16*)(dyn + GSM_A_L);
    __nv_bfloat16* sBH = (__nv_bfloat16*)(dyn + GSM_B_H);
    __nv_bfloat16* sBL = (__nv_bfloat16*)(dyn + GSM_B_L);

    int tid = threadIdx.x, lane = tid & 31, wid = tid >> 5;
    int warpM = wid & 3, warpN = wid >> 2;
    int m0 = blockIdx.y * 128, n0 = blockIdx.x * 128;
    int r = lane >> 2, cc = (lane & 3) * 2;

    float acc[2][8][4];
    #pragma unroll
    for (int i = 0; i < 2; i++)
        #pragma unroll
        for (int j = 0; j < 8; j++)
            #pragma unroll
            for (int q = 0; q < 4; q++) acc[i][j][q] = 0.f;

    for (int kc = 0; kc < 256; kc += 64) {
        #pragma unroll
        for (int u = 0; u < 4; u++) {
            int f = tid + u * 256;
            int rr = f >> 3, c8 = f & 7;
            *(uint4*)&sAH[rr * 72 + c8 * 8] =
                *(const uint4*)&A1H[(size_t)(m0 + rr) * 256 + kc + c8 * 8];
            *(uint4*)&sAL[rr * 72 + c8 * 8] =
                *(const uint4*)&A1L[(size_t)(m0 + rr) * 256 + kc + c8 * 8];
            *(uint4*)&sBH[rr * 72 + c8 * 8] =
                *(const uint4*)&BTH[(size_t)(n0 + rr) * 256 + kc + c8 * 8];
            *(uint4*)&sBL[rr * 72 + c8 * 8] =
                *(const uint4*)&BTL[(size_t)(n0 + rr) * 256 + kc + c8 * 8];
        }
        __syncthreads();

        #pragma unroll
        for (int ks = 0; ks < 4; ks++) {
            int k0 = ks * 16;
            uint32_t aH[2][4], aL[2][4];
            #pragma unroll
            for (int mt = 0; mt < 2; mt++) {
                int ar = warpM * 32 + mt * 16 + r;
                int ac = k0 + cc;
                aH[mt][0] = *(uint32_t*)&sAH[ar * 72 + ac];
                aH[mt][1] = *(uint32_t*)&sAH[(ar + 8) * 72 + ac];
                aH[mt][2] = *(uint32_t*)&sAH[ar * 72 + ac + 8];
                aH[mt][3] = *(uint32_t*)&sAH[(ar + 8) * 72 + ac + 8];
                aL[mt][0] = *(uint32_t*)&sAL[ar * 72 + ac];
                aL[mt][1] = *(uint32_t*)&sAL[(ar + 8) * 72 + ac];
                aL[mt][2] = *(uint32_t*)&sAL[ar * 72 + ac + 8];
                aL[mt][3] = *(uint32_t*)&sAL[(ar + 8) * 72 + ac + 8];
            }
            #pragma unroll
            for (int nt = 0; nt < 8; nt++) {
                int bn = warpN * 64 + nt * 8 + r;
                int bc = k0 + cc;
                uint32_t bH[2], bL[2];
                bH[0] = *(uint32_t*)&sBH[bn * 72 + bc];
                bH[1] = *(uint32_t*)&sBH[bn * 72 + bc + 8];
                bL[0] = *(uint32_t*)&sBL[bn * 72 + bc];
                bL[1] = *(uint32_t*)&sBL[bn * 72 + bc + 8];
                #pragma unroll
                for (int mt = 0; mt < 2; mt++) {
                    mma16816(acc[mt][nt], aH[mt], bH);
                    mma16816(acc[mt][nt], aH[mt], bL);
                    mma16816(acc[mt][nt], aL[mt], bH);
                }
            }
        }
        __syncthreads();
    }

    #pragma unroll
    for (int mt = 0; mt < 2; mt++) {
        #pragma unroll
        for (int nt = 0; nt < 8; nt++) {
            int m = m0 + warpM * 32 + mt * 16 + r;
            int n = n0 + warpN * 64 + nt * 8 + cc;
            unsigned short h0, l0, h1, l1, h2, l2, h3, l3;
            bsplit(acc[mt][nt][0], h0, l0); bsplit(acc[mt][nt][1], h1, l1);
            bsplit(acc[mt][nt][2], h2, l2); bsplit(acc[mt][nt][3], h3, l3);
            *(uint32_t*)&CH[(size_t)m * 256 + n] = pack2(h0, h1);
            *(uint32_t*)&CL[(size_t)m * 256 + n] = pack2(l0, l1);
            *(uint32_t*)&CH[(size_t)(m + 8) * 256 + n] = pack2(h2, h3);
            *(uint32_t*)&CL[(size_t)(m + 8) * 256 + n] = pack2(l2, l3);
        }
    }
}

// ---------------------------------------------------------------------------
// Combine weights: w[s][m] = exp(m_s - M) / sum_s exp(m_s - M) * l_s
// ---------------------------------------------------------------------------
__global__ __launch_bounds__(256)
void weights_kernel()
{
    int m = blockIdx.x * 256 + threadIdx.x;
    int b = m >> 10;
    int len = g_lengths[b];
    int nsl = min(NSLICE, (len + SLICE_S - 1) / SLICE_S);

    float mv[4], lv[4];
    float M = -1e30f;
    for (int s = 0; s < nsl; s++) {
        mv[s] = g_pm[s * MTOT + m];
        lv[s] = g_pl[s * MTOT + m];
        M = fmaxf(M, mv[s]);
    }
    float L = 0.f, ws[4];
    for (int s = 0; s < nsl; s++) {
        float e = __expf(mv[s] - M);
        ws[s] = e;
        L += e * lv[s];
    }
    float inv = 1.0f / L;
    #pragma unroll
    for (int s = 0; s < 4; s++)
        g_wcomb[s * MTOT + m] = (s < nsl) ? ws[s] * inv : 0.f;
}

// ---------------------------------------------------------------------------
// GEMM3 fused with combine: out = tanh([ctx | dec] @ W_fin), where ctx is
// merged in-register from the fp32 split-KV partials during A-staging.
// ---------------------------------------------------------------------------
__global__ __launch_bounds__(256, 2)
void mma_gemm3_fused(const __nv_bfloat16* __restrict__ decH,
                     const __nv_bfloat16* __restrict__ decL,
                     const __nv_bfloat16* __restrict__ BTH,
                     const __nv_bfloat16* __restrict__ BTL,
                     float* __restrict__ out)
{
    extern __shared__ char dyn[];
    __nv_bfloat16* sAH = (__nv_bfloat16*)(dyn + GSM_A_H);
    __nv_bfloat16* sAL = (__nv_bfloat16*)(dyn + GSM_A_L);
    __nv_bfloat16* sBH = (__nv_bfloat16*)(dyn + GSM_B_H);
    __nv_bfloat16* sBL = (__nv_bfloat16*)(dyn + GSM_B_L);

    int tid = threadIdx.x, lane = tid & 31, wid = tid >> 5;
    int warpM = wid & 3, warpN = wid >> 2;
    int m0 = blockIdx.y * 128, n0 = blockIdx.x * 128;
    int r = lane >> 2, cc = (lane & 3) * 2;

    // per-thread combine weights for the rows this thread stages (row rr is
    // fixed across k-chunks for each u)
    float wreg[4][4];   // [u][slice]
    #pragma unroll
    for (int u = 0; u < 4; u++) {
        int rr = (tid + u * 256) >> 3;
        int m = m0 + rr;
        #pragma unroll
        for (int s = 0; s < 4; s++)
            wreg[u][s] = g_wcomb[s * MTOT + m];
    }

    float acc[2][8][4];
    #pragma unroll
    for (int i = 0; i < 2; i++)
        #pragma unroll
        for (int j = 0; j < 8; j++)
            #pragma unroll
            for (int q = 0; q < 4; q++) acc[i][j][q] = 0.f;

    for (int kc = 0; kc < 512; kc += 64) {
        if (kc < 256) {
            // A = combined context (fp32 partials, weighted, split to hi/lo)
            #pragma unroll
            for (int u = 0; u < 4; u++) {
                int f = tid + u * 256;
                int rr = f >> 3, c8 = f & 7;
                int m = m0 + rr;
                float v[8] = {0, 0, 0, 0, 0, 0, 0, 0};
                #pragma unroll
                for (int s = 0; s < 4; s++) {
                    float w = wreg[u][s];
                    const float* p =
                        &g_pctx[((size_t)s * MTOT + m) * 256 + kc + c8 * 8];
                    float4 a = *(const float4*)p;
                    float4 bq = *(const float4*)(p + 4);
                    v[0] += w * a.x;  v[1] += w * a.y;
                    v[2] += w * a.z;  v[3] += w * a.w;
                    v[4] += w * bq.x; v[5] += w * bq.y;
                    v[6] += w * bq.z; v[7] += w * bq.w;
                }
                ushort4 hv, lv, hv2, lv2;
                bsplit(v[0], hv.x, lv.x);  bsplit(v[1], hv.y, lv.y);
                bsplit(v[2], hv.z, lv.z);  bsplit(v[3], hv.w, lv.w);
                bsplit(v[4], hv2.x, lv2.x); bsplit(v[5], hv2.y, lv2.y);
                bsplit(v[6], hv2.z, lv2.z); bsplit(v[7], hv2.w, lv2.w);
                *(ushort4*)&sAH[rr * 72 + c8 * 8] = hv;
                *(ushort4*)&sAH[rr * 72 + c8 * 8 + 4] = hv2;
                *(ushort4*)&sAL[rr * 72 + c8 * 8] = lv;
                *(ushort4*)&sAL[rr * 72 + c8 * 8 + 4] = lv2;
            }
        } else {
            int kcol = kc - 256;
            #pragma unroll
            for (int u = 0; u < 4; u++) {
                int f = tid + u * 256;
                int rr = f >> 3, c8 = f & 7;
                *(uint4*)&sAH[rr * 72 + c8 * 8] =
                    *(const uint4*)&decH[(size_t)(m0 + rr) * 256 + kcol + c8 * 8];
                *(uint4*)&sAL[rr * 72 + c8 * 8] =
                    *(const uint4*)&decL[(size_t)(m0 + rr) * 256 + kcol + c8 * 8];
            }
        }
        // B staging (W_fin^T, stride 512)
        #pragma unroll
        for (int u = 0; u < 4; u++) {
            int f = tid + u * 256;
            int rr = f >> 3, c8 = f & 7;
            *(uint4*)&sBH[rr * 72 + c8 * 8] =
                *(const uint4*)&BTH[(size_t)(n0 + rr) * 512 + kc + c8 * 8];
            *(uint4*)&sBL[rr * 72 + c8 * 8] =
                *(const uint4*)&BTL[(size_t)(n0 + rr) * 512 + kc + c8 * 8];
        }
        __syncthreads();

        #pragma unroll
        for (int ks = 0; ks < 4; ks++) {
            int k0 = ks * 16;
            uint32_t aH[2][4], aL[2][4];
            #pragma unroll
            for (int mt = 0; mt < 2; mt++) {
                int ar = warpM * 32 + mt * 16 + r;
                int ac = k0 + cc;
                aH[mt][0] = *(uint32_t*)&sAH[ar * 72 + ac];
                aH[mt][1] = *(uint32_t*)&sAH[(ar + 8) * 72 + ac];
                aH[mt][2] = *(uint32_t*)&sAH[ar * 72 + ac + 8];
                aH[mt][3] = *(uint32_t*)&sAH[(ar + 8) * 72 + ac + 8];
                aL[mt][0] = *(uint32_t*)&sAL[ar * 72 + ac];
                aL[mt][1] = *(uint32_t*)&sAL[(ar + 8) * 72 + ac];
                aL[mt][2] = *(uint32_t*)&sAL[ar * 72 + ac + 8];
                aL[mt][3] = *(uint32_t*)&sAL[(ar + 8) * 72 + ac + 8];
            }
            #pragma unroll
            for (int nt = 0; nt < 8; nt++) {
                int bn = warpN * 64 + nt * 8 + r;
                int bc = k0 + cc;
                uint32_t bH[2], bL[2];
                bH[0] = *(uint32_t*)&sBH[bn * 72 + bc];
                bH[1] = *(uint32_t*)&sBH[bn * 72 + bc + 8];
                bL[0] = *(uint32_t*)&sBL[bn * 72 + bc];
                bL[1] = *(uint32_t*)&sBL[bn * 72 + bc + 8];
                #pragma unroll
                for (int mt = 0; mt < 2; mt++) {
                    mma16816(acc[mt][nt], aH[mt], bH);
                    mma16816(acc[mt][nt], aH[mt], bL);
                    mma16816(acc[mt][nt], aL[mt], bH);
                }
            }
        }
        __syncthreads();
    }

    #pragma unroll
    for (int mt = 0; mt < 2; mt++) {
        #pragma unroll
        for (int nt = 0; nt < 8; nt++) {
            int m = m0 + warpM * 32 + mt * 16 + r;
            int n = n0 + warpN * 64 + nt * 8 + cc;
            float2 v0 = make_float2(tanhf(acc[mt][nt][0]), tanhf(acc[mt][nt][1]));
            float2 v1 = make_float2(tanhf(acc[mt][nt][2]), tanhf(acc[mt][nt][3]));
            *(float2*)&out[(size_t)m * 256 + n] = v0;
            *(float2*)&out[(size_t)(m + 8) * 256 + n] = v1;
        }
    }
}

// ---------------------------------------------------------------------------
// Fused flash attention (round-7 committed version, unchanged)
// ---------------------------------------------------------------------------
#define O_AH0 0
#define O_AL0 9216
#define O_AH1 18432
#define O_AL1 27648
#define O_E   36864
#define O_PMAX 110592
#define O_PSUM 111104
#define A_TOTAL 111616

__device__ __forceinline__ void stage_chunk(uint32_t base, int abuf, int ch,
                                            size_t dpBase, size_t encBase,
                                            int s0, int tid)
{
    uint32_t ah = base + (abuf ? O_AH1 : O_AH0);
    uint32_t al = ah + 9216;
    uint32_t eh = base + O_E + ch * 18432;
    uint32_t el = eh + 9216;
    int kc = ch * 64;
    #pragma unroll
    for (int u = 0; u < 2; u++) {
        int f = tid + u * 256;
        int rr = f >> 3, c = f & 7;
        uint32_t doff = rr * 144 + c * 16;
        size_t ga = dpBase + (size_t)rr * 256 + kc + c * 8;
        size_t ge = encBase + (size_t)(s0 + rr) * 256 + kc + c * 8;
        cp16(ah + doff, g_dpH + ga);
        cp16(al + doff, g_dpL + ga);
        cp16(eh + doff, g_encH + ge);
        cp16(el + doff, g_encL + ge);
    }
}

__global__ __launch_bounds__(256, 2)
void attn_kernel()
{
    extern __shared__ char dyn[];
    uint32_t base = smem_u32(dyn);
    float* sPmax = (float*)(dyn + O_PMAX);
    float* sPsum = (float*)(dyn + O_PSUM);
    __nv_bfloat16* pH = (__nv_bfloat16*)(dyn + O_AH1);
    __nv_bfloat16* pL = (__nv_bfloat16*)(dyn + O_AL1);

    int tid = threadIdx.x, lane = tid & 31, wid = tid >> 5;
    int warpT = wid & 3;
    int warpS = wid >> 2;
    int r = lane >> 2, cc = (lane & 3) * 2;
    int b = blockIdx.y;
    int t0 = blockIdx.x * 64;
    int slice = blockIdx.z;
    int len = g_lengths[b];

    int sbeg = slice * SLICE_S;
    if (sbeg >= len) return;
    int send = min(sbeg + SLICE_S, len);

    size_t dpBase = ((size_t)b * Tt + t0) * 256;
    size_t encBase = (size_t)b * Ss * 256;

    int row0 = warpT * 16 + r;
    int row1 = row0 + 8;
    float mreg0 = -1e30f, mreg1 = -1e30f;
    float lreg0 = 0.f, lreg1 = 0.f;

    float ctx[4][4][4];
    #pragma unroll
    for (int i = 0; i < 4; i++)
        #pragma unroll
        for (int j = 0; j < 4; j++)
            #pragma unroll
            for (int q = 0; q < 4; q++) ctx[i][j][q] = 0.f;

    stage_chunk(base, 0, 0, dpBase, encBase, sbeg, tid);
    CP_COMMIT();

    for (int s0 = sbeg; s0 < send; s0 += 64) {
        bool have_next = (s0 + 64 < send);

        float sacc[4][4];
        #pragma unroll
        for (int j = 0; j < 4; j++)
            #pragma unroll
            for (int q = 0; q < 4; q++) sacc[j][q] = 0.f;

        #pragma unroll
        for (int kch = 0; kch < 4; kch++) {
            if (kch < 3) {
                stage_chunk(base, (kch + 1) & 1, kch + 1, dpBase, encBase,
                            s0, tid);
                CP_COMMIT();
                CP_WAIT(1);
            } else {
                CP_WAIT(0);
            }
            __syncthreads();

            const __nv_bfloat16* sAH =
                (const __nv_bfloat16*)(dyn + ((kch & 1) ? O_AH1 : O_AH0));
            const __nv_bfloat16* sAL = sAH + 4608;
            const __nv_bfloat16* sBH =
                (const __nv_bfloat16*)(dyn + O_E + kch * 18432);
            const __nv_bfloat16* sBL = sBH + 4608;

            #pragma unroll
            for (int ks = 0; ks < 4; ks++) {
                int ac = ks * 16 + cc;
                int ar = warpT * 16 + r;
                uint32_t aH[4], aL[4];
                aH[0] = *(uint32_t*)&sAH[ar * 72 + ac];
                aH[1] = *(uint32_t*)&sAH[(ar + 8) * 72 + ac];
                aH[2] = *(uint32_t*)&sAH[ar * 72 + ac + 8];
                aH[3] = *(uint32_t*)&sAH[(ar + 8) * 72 + ac + 8];
                aL[0] = *(uint32_t*)&sAL[ar * 72 + ac];
                aL[1] = *(uint32_t*)&sAL[(ar + 8) * 72 + ac];
                aL[2] = *(uint32_t*)&sAL[ar * 72 + ac + 8];
                aL[3] = *(uint32_t*)&sAL[(ar + 8) * 72 + ac + 8];
                #pragma unroll
                for (int nt = 0; nt < 4; nt++) {
                    int bn = warpS * 32 + nt * 8 + r;
                    uint32_t bH[2], bL[2];
                    bH[0] = *(uint32_t*)&sBH[bn * 72 + ac];
                    bH[1] = *(uint32_t*)&sBH[bn * 72 + ac + 8];
                    bL[0] = *(uint32_t*)&sBL[bn * 72 + ac];
                    bL[1] = *(uint32_t*)&sBL[bn * 72 + ac + 8];
                    mma16816(sacc[nt], aH, bH);
                    mma16816(sacc[nt], aH, bL);
                    mma16816(sacc[nt], aL, bH);
                }
            }
            __syncthreads();
        }

        // register softmax
        float rm0 = -1e30f, rm1 = -1e30f;
        #pragma unroll
        for (int nt = 0; nt < 4; nt++) {
            int cg = s0 + warpS * 32 + nt * 8 + cc;
            if (cg >= len)     { sacc[nt][0] = -1e30f; sacc[nt][2] = -1e30f; }
            if (cg + 1 >= len) { sacc[nt][1] = -1e30f; sacc[nt][3] = -1e30f; }
            rm0 = fmaxf(rm0, fmaxf(sacc[nt][0], sacc[nt][1]));
            rm1 = fmaxf(rm1, fmaxf(sacc[nt][2], sacc[nt][3]));
        }
        rm0 = fmaxf(rm0, __shfl_xor_sync(0xffffffffu, rm0, 1));
        rm0 = fmaxf(rm0, __shfl_xor_sync(0xffffffffu, rm0, 2));
        rm1 = fmaxf(rm1, __shfl_xor_sync(0xffffffffu, rm1, 1));
        rm1 = fmaxf(rm1, __shfl_xor_sync(0xffffffffu, rm1, 2));
        if ((lane & 3) == 0) {
            sPmax[row0 * 2 + warpS] = rm0;
            sPmax[row1 * 2 + warpS] = rm1;
        }
        __syncthreads();

        float mN0 = fmaxf(mreg0, fmaxf(sPmax[row0 * 2], sPmax[row0 * 2 + 1]));
        float mN1 = fmaxf(mreg1, fmaxf(sPmax[row1 * 2], sPmax[row1 * 2 + 1]));
        float scl0 = __expf(mreg0 - mN0);
        float scl1 = __expf(mreg1 - mN1);
        mreg0 = mN0; mreg1 = mN1;

        float sum0 = 0.f, sum1 = 0.f;
        #pragma unroll
        for (int nt = 0; nt < 4; nt++) {
            sacc[nt][0] = __expf(sacc[nt][0] - mN0);
            sacc[nt][1] = __expf(sacc[nt][1] - mN0);
            sacc[nt][2] = __expf(sacc[nt][2] - mN1);
            sacc[nt][3] = __expf(sacc[nt][3] - mN1);
            sum0 += sacc[nt][0] + sacc[nt][1];
            sum1 += sacc[nt][2] + sacc[nt][3];
        }
        sum0 += __shfl_xor_sync(0xffffffffu, sum0, 1);
        sum0 += __shfl_xor_sync(0xffffffffu, sum0, 2);
        sum1 += __shfl_xor_sync(0xffffffffu, sum1, 1);
        sum1 += __shfl_xor_sync(0xffffffffu, sum1, 2);
        if ((lane & 3) == 0) {
            sPsum[row0 * 2 + warpS] = sum0;
            sPsum[row1 * 2 + warpS] = sum1;
        }
        #pragma unroll
        for (int nt = 0; nt < 4; nt++) {
            int colb = warpS * 32 + nt * 8 + cc;
            unsigned short h0, l0, h1, l1, h2, l2, h3, l3;
            bsplit(sacc[nt][0], h0, l0); bsplit(sacc[nt][1], h1, l1);
            bsplit(sacc[nt][2], h2, l2); bsplit(sacc[nt][3], h3, l3);
            *(uint32_t*)&pH[row0 * 72 + colb] = pack2(h0, h1);
            *(uint32_t*)&pL[row0 * 72 + colb] = pack2(l0, l1);
            *(uint32_t*)&pH[row1 * 72 + colb] = pack2(h2, h3);
            *(uint32_t*)&pL[row1 * 72 + colb] = pack2(l2, l3);
        }
        __syncthreads();

        lreg0 = lreg0 * scl0 + sPsum[row0 * 2] + sPsum[row0 * 2 + 1];
        lreg1 = lreg1 * scl1 + sPsum[row1 * 2] + sPsum[row1 * 2 + 1];
        #pragma unroll
        for (int i = 0; i < 4; i++)
            #pragma unroll
            for (int j = 0; j < 4; j++) {
                ctx[i][j][0] *= scl0; ctx[i][j][1] *= scl0;
                ctx[i][j][2] *= scl1; ctx[i][j][3] *= scl1;
            }

        // context GEMM (reuse E chunks)
        #pragma unroll
        for (int ch = 0; ch < 4; ch++) {
            uint32_t ehb = base + O_E + ch * 18432;
            uint32_t elb = ehb + 9216;
            #pragma unroll
            for (int ks = 0; ks < 4; ks++) {
                int ac = ks * 16 + cc;
                int ar = warpT * 16 + r;
                uint32_t aH[4], aL[4];
                aH[0] = *(uint32_t*)&pH[ar * 72 + ac];
                aH[1] = *(uint32_t*)&pH[(ar + 8) * 72 + ac];
                aH[2] = *(uint32_t*)&pH[ar * 72 + ac + 8];
                aH[3] = *(uint32_t*)&pH[(ar + 8) * 72 + ac + 8];
                aL[0] = *(uint32_t*)&pL[ar * 72 + ac];
                aL[1] = *(uint32_t*)&pL[(ar + 8) * 72 + ac];
                aL[2] = *(uint32_t*)&pL[ar * 72 + ac + 8];
                aL[3] = *(uint32_t*)&pL[(ar + 8) * 72 + ac + 8];
                uint32_t lrow = (uint32_t)(ks * 16 + (lane & 15));
                uint32_t lcol0 = (uint32_t)(warpS * 32 + ((lane >> 4) << 3));
                #pragma unroll
                for (int pair = 0; pair < 2; pair++) {
                    uint32_t off = (lrow * 72 + lcol0 + pair * 16) * 2;
                    uint32_t bh0, bh1, bh2, bh3, bl0, bl1, bl2, bl3;
                    ldsm_x4_t(bh0, bh1, bh2, bh3, ehb + off);
                    ldsm_x4_t(bl0, bl1, bl2, bl3, elb + off);
                    uint32_t bH0[2] = {bh0, bh1}, bH1[2] = {bh2, bh3};
                    uint32_t bL0[2] = {bl0, bl1}, bL1[2] = {bl2, bl3};
                    int nt = pair * 2;
                    mma16816(ctx[ch][nt], aH, bH0);
                    mma16816(ctx[ch][nt], aH, bL0);
                    mma16816(ctx[ch][nt], aL, bH0);
                    mma16816(ctx[ch][nt + 1], aH, bH1);
                    mma16816(ctx[ch][nt + 1], aH, bL1);
                    mma16816(ctx[ch][nt + 1], aL, bH1);
                }
            }
            if (ch == 0) {
                __syncthreads();
                if (have_next) {
                    stage_chunk(base, 0, 0, dpBase, encBase, s0 + 64, tid);
                    CP_COMMIT();
                }
            }
        }
        __syncthreads();
    }

    // write partials
    size_t pmBase = (((size_t)slice * Bb + b) * Tt) + t0;
    if (warpS == 0 && (lane & 3) == 0) {
        g_pm[pmBase + row0] = mreg0;
        g_pm[pmBase + row1] = mreg1;
        g_pl[pmBase + row0] = lreg0;
        g_pl[pmBase + row1] = lreg1;
    }
    int t = t0 + row0;
    size_t obase = (((size_t)slice * Bb + b) * Tt + t) * 256;
    #pragma unroll
    for (int ch = 0; ch < 4; ch++) {
        #pragma unroll
        for (int nt = 0; nt < 4; nt++) {
            int e = ch * 64 + warpS * 32 + nt * 8 + cc;
            *(float2*)&g_pctx[obase + e] =
                make_float2(ctx[ch][nt][0], ctx[ch][nt][1]);
            *(float2*)&g_pctx[obase + 8 * 256 + e] =
                make_float2(ctx[ch][nt][2], ctx[ch][nt][3]);
        }
    }
}

// ---------------------------------------------------------------------------
extern "C" void kernel_launch(void* const* d_in, const int* in_sizes, int n_in,
                              void* d_out, int out_size)
{
    (void)in_sizes; (void)n_in; (void)out_size;
    const float* enc = (const float*)d_in[0];
    const float* dec = (const float*)d_in[1];
    const unsigned char* mask = (const unsigned char*)d_in[2];
    const float* W_enc = (const float*)d_in[3];
    const float* W_fin = (const float*)d_in[4];
    float* out = (float*)d_out;

    void *pDecH, *pDecL, *pDpH, *pDpL, *pWeH, *pWeL, *pWfH, *pWfL;
    cudaGetSymbolAddress(&pDecH, g_decH);
    cudaGetSymbolAddress(&pDecL, g_decL);
    cudaGetSymbolAddress(&pDpH, g_dpH);
    cudaGetSymbolAddress(&pDpL, g_dpL);
    cudaGetSymbolAddress(&pWeH, g_WencH);
    cudaGetSymbolAddress(&pWeL, g_WencL);
    cudaGetSymbolAddress(&pWfH, g_WfinTH);
    cudaGetSymbolAddress(&pWfL, g_WfinTL);

    cudaFuncSetAttribute((const void*)mma_gemm1_kernel,
                         cudaFuncAttributeMaxDynamicSharedMemorySize, GSM_TOTAL);
    cudaFuncSetAttribute((const void*)mma_gemm3_fused,
                         cudaFuncAttributeMaxDynamicSharedMemorySize, GSM_TOTAL);
    cudaFuncSetAttribute((const void*)attn_kernel,
                         cudaFuncAttributeMaxDynamicSharedMemorySize, A_TOTAL);

    detect_lengths_kernel<<<1, 256>>>(mask);
    prep_convert_kernel<<<1024, 256>>>(enc, dec, W_enc, W_fin);

    // GEMM1': decproj = dec @ W_enc^T
    dim3 g1(2, 128);
    mma_gemm1_kernel<<<g1, 256, GSM_TOTAL>>>(
        (const __nv_bfloat16*)pDecH, (const __nv_bfloat16*)pDecL,
        (const __nv_bfloat16*)pWeH, (const __nv_bfloat16*)pWeL,
        (__nv_bfloat16*)pDpH, (__nv_bfloat16*)pDpL);

    dim3 g2(Tt / 64, Bb, NSLICE);
    attn_kernel<<<g2, 256, A_TOTAL>>>();

    weights_kernel<<<MTOT / 256, 256>>>();

    // GEMM3 fused with combine
    dim3 g3(2, 128);
    mma_gemm3_fused<<<g3, 256, GSM_TOTAL>>>(
        (const __nv_bfloat16*)pDecH, (const __nv_bfloat16*)pDecL,
        (const __nv_bfloat16*)pWfH, (const __nv_bfloat16*)pWfL,
        out);
}